// round 9
// baseline (speedup 1.0000x reference)
#include <cuda_runtime.h>
#include <cstdint>

#define RR 5
#define NN 4096
#define DD 256
#define HH 64
#define BB 4096

// ---------------- scratch (static device globals; no allocs allowed) -------
__device__ float g_uw[RR*DD*HH];            // cumsum(u_weight)
__device__ float g_vw[RR*DD*HH];            // cumsum(v_weight)
__device__ float g_rowPart[RR*32*NN];       // [r][mchunk][n]
__device__ float g_colPart[RR*16*NN];       // [r][nchunk][m]
__device__ float g_cinv[RR*NN];             // index n
__device__ float g_rinv[RR*NN];             // index m
__device__ float g_Xh[(size_t)RR*HH*NN];    // X^T (tf32-rounded) [r][h][n]
__device__ float g_Y [(size_t)RR*NN*HH];    // Y   (tf32-rounded) [r][m][h]
__device__ float g_Tu[(size_t)RR*NN*HH];    // [r][n][h]
__device__ float g_Tvt[(size_t)RR*HH*NN];   // [r][h][m]

// ---------------- pass 1: row/col sums of support --------------------------
// grid (32, 16, RR), block 128. mc: 128-col chunk of m; nc: 256-row chunk of n.
__global__ void k_sums(const float* __restrict__ supp){
  const int r = blockIdx.z, mc = blockIdx.x, nc = blockIdx.y;
  const int m0 = mc*128, n0 = nc*256;
  const int w = threadIdx.x>>5, lane = threadIdx.x&31;
  const float* base = supp + (size_t)r*NN*NN + m0 + lane*4;
  float cx=0.f, cy=0.f, cz=0.f, cw=0.f;
  float* rp = g_rowPart + ((size_t)r*32 + mc)*NN;
  #pragma unroll 4
  for(int i=0;i<64;i++){
    const int n = n0 + w*64 + i;
    const float4 v = *reinterpret_cast<const float4*>(base + (size_t)n*NN);
    float s = v.x+v.y+v.z+v.w;
    cx+=v.x; cy+=v.y; cz+=v.z; cw+=v.w;
    #pragma unroll
    for(int o=16;o;o>>=1) s += __shfl_xor_sync(0xffffffffu, s, o);
    if(lane==0) rp[n] = s;
  }
  __shared__ float sc[4][128];
  sc[w][lane*4+0]=cx; sc[w][lane*4+1]=cy; sc[w][lane*4+2]=cz; sc[w][lane*4+3]=cw;
  __syncthreads();
  if(threadIdx.x < 128){
    float s = sc[0][threadIdx.x]+sc[1][threadIdx.x]+sc[2][threadIdx.x]+sc[3][threadIdx.x];
    g_colPart[((size_t)r*16 + nc)*NN + m0 + threadIdx.x] = s;
  }
}

__global__ void k_reduce(){
  const int idx = blockIdx.x*256 + threadIdx.x;
  if(idx < RR*NN){
    const int r = idx/NN, n = idx%NN;
    float s=0.f;
    #pragma unroll
    for(int mc=0; mc<32; mc++) s += g_rowPart[((size_t)r*32+mc)*NN + n];
    g_cinv[idx] = (s>0.f)? rsqrtf(s) : 0.f;
  } else {
    const int j = idx - RR*NN;
    const int r = j/NN, m = j%NN;
    float s=0.f;
    #pragma unroll
    for(int nc=0; nc<16; nc++) s += g_colPart[((size_t)r*16+nc)*NN + m];
    g_rinv[j] = (s>0.f)? rsqrtf(s) : 0.f;
  }
}

__global__ void k_weights(const float* __restrict__ uw, const float* __restrict__ vw){
  const int i = blockIdx.x*256 + threadIdx.x;
  float au=0.f, av=0.f;
  #pragma unroll
  for(int r=0;r<RR;r++){
    au += uw[r*DD*HH + i]; g_uw[r*DD*HH + i] = au;
    av += vw[r*DD*HH + i]; g_vw[r*DD*HH + i] = av;
  }
}

// ---------------- TF32 / mma helpers ---------------------------------------
__device__ __forceinline__ unsigned f2tf(float x){
  unsigned r; asm("cvt.rna.tf32.f32 %0, %1;" : "=r"(r) : "f"(x)); return r;
}
__device__ __forceinline__ void mma8(float* c, const unsigned* a, const unsigned* b){
  asm volatile("mma.sync.aligned.m16n8k8.row.col.f32.tf32.tf32.f32 "
    "{%0,%1,%2,%3},{%4,%5,%6,%7},{%8,%9},{%0,%1,%2,%3};"
    : "+f"(c[0]),"+f"(c[1]),"+f"(c[2]),"+f"(c[3])
    : "r"(a[0]),"r"(a[1]),"r"(a[2]),"r"(a[3]),"r"(b[0]),"r"(b[1]));
}
__device__ __forceinline__ void cpa16(uint32_t dst, const void* src){
  asm volatile("cp.async.cg.shared.global [%0], [%1], 16;" :: "r"(dst), "l"(src));
}
#define CP_COMMIT asm volatile("cp.async.commit_group;" ::: "memory")
#define CP_WAIT1  asm volatile("cp.async.wait_group 1;"  ::: "memory")

// K-chunk 32 smem layout (word strides):
// A: rows x 32 words, stride 36 -> frag banks (4*l4+lc) distinct.
// B: 32 k-rows x 64/128 words, stride 72/136 (==8 mod 32) -> banks (8*lc+l4) distinct.
#define A_STR 36
#define BU_STR 72
#define BV_STR 136
#define STG_WORDS (128*A_STR + 32*BU_STR)   // 6912 words = 27648 B (z1 needs 6656)
#define STG_BYTES (STG_WORDS*4)
#define DYN_BYTES (2*STG_BYTES)             // 55296 B, 2 stages, occupancy 3

template<int BS>
__device__ __forceinline__ void load_frag(const unsigned* __restrict__ Ab,
                                          const unsigned* __restrict__ Bb,
                                          int wm,int wn,int l4,int lc,int k8,
                                          unsigned a[2][4], unsigned b[4][2]){
  #pragma unroll
  for(int mi=0; mi<2; mi++){
    const int rr = wm*32 + mi*16 + l4;
    a[mi][0]=Ab[rr*A_STR     + k8+lc];
    a[mi][1]=Ab[(rr+8)*A_STR + k8+lc];
    a[mi][2]=Ab[rr*A_STR     + k8+lc+4];
    a[mi][3]=Ab[(rr+8)*A_STR + k8+lc+4];
  }
  #pragma unroll
  for(int ni=0; ni<4; ni++){
    const int cc = wn*32 + ni*8 + l4;
    b[ni][0]=Bb[(k8+lc)*BS   + cc];
    b[ni][1]=Bb[(k8+lc+4)*BS + cc];
  }
}

template<int BS>
__device__ __forceinline__ void chunk_mma(const unsigned* __restrict__ Ab,
                                          const unsigned* __restrict__ Bb,
                                          int wm,int wn,int l4,int lc,
                                          float acc[2][4][4]){
  unsigned a[2][2][4], b[2][4][2];
  load_frag<BS>(Ab,Bb,wm,wn,l4,lc,0,a[0],b[0]);
  #pragma unroll
  for(int ks=0; ks<4; ks++){
    const int cur = ks&1;
    if(ks<3) load_frag<BS>(Ab,Bb,wm,wn,l4,lc,(ks+1)*8,a[cur^1],b[cur^1]);
    #pragma unroll
    for(int ni=0; ni<4; ni++){
      mma8(acc[0][ni], a[cur][0], b[cur][ni]);
      mma8(acc[1][ni], a[cur][1], b[cur][ni]);
    }
  }
}

// ---------------- k_tmp2: Xh / Y via mma, K-chunk 32 -----------------------
// side 0: Xh[r][h][n] = tf32( (u_feat @ cum_uw)[n][h] * cinv[r][n] )
// side 1: Y [r][m][h] = tf32( (v_feat @ cum_vw)[m][h] * rinv[r][m] )
__global__ __launch_bounds__(128) void k_tmp2(const float* __restrict__ uf,
                                              const float* __restrict__ vf){
  __shared__ __align__(16) unsigned smA[64*A_STR];
  __shared__ __align__(16) unsigned smB[32*BU_STR];
  const int side = blockIdx.z, r = blockIdx.y, n0 = blockIdx.x*64;
  const int tid = threadIdx.x;
  const int wid = tid>>5, lane = tid&31, l4 = lane>>2, lc = lane&3;
  const int wm = wid&1, wn = wid>>1;
  const float* feat = (side ? vf : uf) + (size_t)n0*DD;
  const float* wgt  = (side ? g_vw : g_uw) + r*DD*HH;
  float acc[2][4][4];
  #pragma unroll
  for(int i=0;i<2;i++) for(int j=0;j<4;j++) for(int k=0;k<4;k++) acc[i][j][k]=0.f;

  for(int k0=0; k0<DD; k0+=32){
    #pragma unroll
    for(int i=0;i<4;i++){                      // A 64x32 raw
      const int f = tid + i*128, row = f>>3, c = (f&7)*4;
      *reinterpret_cast<uint4*>(smA + row*A_STR + c) =
        *reinterpret_cast<const uint4*>(feat + (size_t)row*DD + k0 + c);
    }
    #pragma unroll
    for(int i=0;i<4;i++){                      // B 32x64 raw
      const int f = tid + i*128, row = f>>4, c = (f&15)*4;
      *reinterpret_cast<uint4*>(smB + row*BU_STR + c) =
        *reinterpret_cast<const uint4*>(wgt + (size_t)(k0+row)*HH + c);
    }
    __syncthreads();
    chunk_mma<BU_STR>(smA, smB, wm, wn, l4, lc, acc);
    __syncthreads();
  }
  const float* sv = (side ? g_rinv : g_cinv) + r*NN;
  #pragma unroll
  for(int mi=0; mi<2; mi++){
    const int n = n0 + wm*32 + mi*16 + l4;
    const float s0 = sv[n], s1 = sv[n+8];
    #pragma unroll
    for(int ni=0; ni<4; ni++){
      const int h = wn*32 + ni*8 + lc*2;
      if(side==0){
        g_Xh[((size_t)r*HH + h  )*NN + n  ] = __uint_as_float(f2tf(acc[mi][ni][0]*s0));
        g_Xh[((size_t)r*HH + h+1)*NN + n  ] = __uint_as_float(f2tf(acc[mi][ni][1]*s0));
        g_Xh[((size_t)r*HH + h  )*NN + n+8] = __uint_as_float(f2tf(acc[mi][ni][2]*s1));
        g_Xh[((size_t)r*HH + h+1)*NN + n+8] = __uint_as_float(f2tf(acc[mi][ni][3]*s1));
      } else {
        g_Y[((size_t)r*NN + n  )*HH + h  ] = __uint_as_float(f2tf(acc[mi][ni][0]*s0));
        g_Y[((size_t)r*NN + n  )*HH + h+1] = __uint_as_float(f2tf(acc[mi][ni][1]*s0));
        g_Y[((size_t)r*NN + n+8)*HH + h  ] = __uint_as_float(f2tf(acc[mi][ni][2]*s1));
        g_Y[((size_t)r*NN + n+8)*HH + h+1] = __uint_as_float(f2tf(acc[mi][ni][3]*s1));
      }
    }
  }
}

// ---------------- dominant kernel: dual GEMM, K32, 2-stage, occ 3 ----------
// z=0:  T_u[r][n][h]  = sum_m supp[r][n][m] * Y[r][m][h]   (CTA 128n x 64h)
// z=1:  Tvt[r][h][m]  = sum_n Xh[r][h][n] * supp[r][n][m]  (CTA 64h x 128m)
// support fed raw (HW tf32 truncation); Y/Xh pre-rounded tf32.
__global__ __launch_bounds__(256,3) void k_gemm(const float* __restrict__ supp){
  extern __shared__ __align__(16) unsigned char smbuf[];
  const int r = blockIdx.y;
  const int tid = threadIdx.x;
  const int wid = tid>>5, lane = tid&31, l4 = lane>>2, lc = lane&3;
  const uint32_t smb = (uint32_t)__cvta_generic_to_shared(smbuf);
  float acc[2][4][4];
  #pragma unroll
  for(int i=0;i<2;i++) for(int j=0;j<4;j++) for(int k=0;k<4;k++) acc[i][j][k]=0.f;

  if(blockIdx.z == 0){
    const int n0 = blockIdx.x*128;
    const int wm = wid & 3, wn = wid >> 2;          // 4x2 warp grid
    const float* A  = supp + ((size_t)r*NN + n0)*NN;
    const float* Bp = g_Y  + (size_t)r*NN*HH;
    auto load = [&](int j){
      const uint32_t sa = smb + (uint32_t)(j&1)*STG_BYTES;
      const uint32_t sb = sa + 128*A_STR*4;
      const int k0 = j*32;
      #pragma unroll
      for(int i=0;i<4;i++){                         // A 128x32
        const int f = tid + i*256, row = f>>3, c = (f&7)*4;
        cpa16(sa + (uint32_t)(row*A_STR + c)*4u, A + (size_t)row*NN + k0 + c);
      }
      #pragma unroll
      for(int i=0;i<2;i++){                         // B 32x64
        const int f = tid + i*256, row = f>>4, c = (f&15)*4;
        cpa16(sb + (uint32_t)(row*BU_STR + c)*4u, Bp + (size_t)(k0+row)*HH + c);
      }
    };
    load(0); CP_COMMIT;
    for(int it=0; it<NN/32; it++){
      if(it+1 < NN/32) load(it+1);
      CP_COMMIT;
      CP_WAIT1; __syncthreads();
      const unsigned* Ab = (const unsigned*)(smbuf + (it&1)*STG_BYTES);
      chunk_mma<BU_STR>(Ab, Ab + 128*A_STR, wm, wn, l4, lc, acc);
      __syncthreads();
    }
    float* Out = g_Tu + ((size_t)r*NN + n0)*HH;
    #pragma unroll
    for(int mi=0; mi<2; mi++){
      const int r0 = wm*32 + mi*16 + l4;
      #pragma unroll
      for(int ni=0; ni<4; ni++){
        const int h = wn*32 + ni*8 + lc*2;
        *reinterpret_cast<float2*>(&Out[(size_t)r0*HH + h])     = make_float2(acc[mi][ni][0], acc[mi][ni][1]);
        *reinterpret_cast<float2*>(&Out[(size_t)(r0+8)*HH + h]) = make_float2(acc[mi][ni][2], acc[mi][ni][3]);
      }
    }
  } else {
    const int m0 = blockIdx.x*128;
    const int wm = wid & 1, wn = wid >> 1;          // 2x4 warp grid
    const float* A  = g_Xh + (size_t)r*HH*NN;       // [h][n]
    const float* Bp = supp + (size_t)r*NN*NN + m0;  // rows n(K), cols m
    auto load = [&](int j){
      const uint32_t sa = smb + (uint32_t)(j&1)*STG_BYTES;
      const uint32_t sb = sa + 64*A_STR*4;
      const int k0 = j*32;
      #pragma unroll
      for(int i=0;i<2;i++){                         // A 64x32
        const int f = tid + i*256, row = f>>3, c = (f&7)*4;
        cpa16(sa + (uint32_t)(row*A_STR + c)*4u, A + (size_t)row*NN + k0 + c);
      }
      #pragma unroll
      for(int i=0;i<4;i++){                         // B 32x128
        const int f = tid + i*256, row = f>>5, c = (f&31)*4;
        cpa16(sb + (uint32_t)(row*BV_STR + c)*4u, Bp + (size_t)(k0+row)*NN + c);
      }
    };
    load(0); CP_COMMIT;
    for(int it=0; it<NN/32; it++){
      if(it+1 < NN/32) load(it+1);
      CP_COMMIT;
      CP_WAIT1; __syncthreads();
      const unsigned* Ab = (const unsigned*)(smbuf + (it&1)*STG_BYTES);
      chunk_mma<BV_STR>(Ab, Ab + 64*A_STR, wm, wn, l4, lc, acc);
      __syncthreads();
    }
    float* Out = g_Tvt + (size_t)r*HH*NN + m0;
    #pragma unroll
    for(int mi=0; mi<2; mi++){
      const int hr = wm*32 + mi*16 + l4;
      #pragma unroll
      for(int ni=0; ni<4; ni++){
        const int mcol = wn*32 + ni*8 + lc*2;
        *reinterpret_cast<float2*>(&Out[(size_t)hr*NN + mcol])     = make_float2(acc[mi][ni][0], acc[mi][ni][1]);
        *reinterpret_cast<float2*>(&Out[(size_t)(hr+8)*NN + mcol]) = make_float2(acc[mi][ni][2], acc[mi][ni][3]);
      }
    }
  }
}

// ---------------- gather + bias + relu -------------------------------------
__global__ void k_out(const int* __restrict__ u, const int* __restrict__ v,
                      const float* __restrict__ bias, float* __restrict__ out){
  const int b = blockIdx.x;
  const int h = threadIdx.x;  // 64
  const int ub = u[b], vb = v[b];
  float su = bias[h], sv = bias[h];
  #pragma unroll
  for(int r=0;r<RR;r++){
    su += g_cinv[r*NN + ub] * g_Tu [((size_t)r*NN + ub)*HH + h];
    sv += g_rinv[r*NN + vb] * g_Tvt[((size_t)r*HH + h)*NN + vb];
  }
  out[(size_t)b*HH + h]        = fmaxf(su, 0.f);
  out[(size_t)(BB + b)*HH + h] = fmaxf(sv, 0.f);
}

// ---------------- launch ----------------------------------------------------
extern "C" void kernel_launch(void* const* d_in, const int* in_sizes, int n_in,
                              void* d_out, int out_size){
  (void)in_sizes; (void)n_in; (void)out_size;
  const float* u_feat = (const float*)d_in[0];
  const float* v_feat = (const float*)d_in[1];
  const int*   u      = (const int*)  d_in[2];
  const int*   v      = (const int*)  d_in[3];
  const float* supp   = (const float*)d_in[4];
  const float* u_w    = (const float*)d_in[5];
  const float* v_w    = (const float*)d_in[6];
  const float* u_bias = (const float*)d_in[7];
  float* out = (float*)d_out;

  static int attr_done = 0;
  if(!attr_done){
    cudaFuncSetAttribute(k_gemm, cudaFuncAttributeMaxDynamicSharedMemorySize, DYN_BYTES);
    attr_done = 1;
  }

  k_sums   <<<dim3(32, 16, RR), 128>>>(supp);
  k_reduce <<<160, 256>>>();
  k_weights<<<64, 256>>>(u_w, v_w);
  k_tmp2   <<<dim3(64, RR, 2), 128>>>(u_feat, v_feat);
  k_gemm   <<<dim3(32, RR, 2), 256, DYN_BYTES>>>(supp);
  k_out    <<<BB, HH>>>(u, v, u_bias, out);
}

// round 10
// speedup vs baseline: 1.4623x; 1.4623x over previous
#include <cuda_runtime.h>
#include <cstdint>

#define RR 5
#define NN 4096
#define DD 256
#define HH 64
#define BB 4096

// ---------------- scratch (static device globals; no allocs allowed) -------
__device__ float g_uw[RR*DD*HH];            // cumsum(u_weight)
__device__ float g_vw[RR*DD*HH];            // cumsum(v_weight)
__device__ float g_rowPart[RR*32*NN];       // [r][mchunk][n]
__device__ float g_colPart[RR*16*NN];       // [r][nchunk][m]
__device__ float g_cinv[RR*NN];             // index n
__device__ float g_rinv[RR*NN];             // index m
__device__ float g_Xh[(size_t)RR*HH*NN];    // X^T (tf32-rounded) [r][h][n]
__device__ float g_Y [(size_t)RR*NN*HH];    // Y   (tf32-rounded) [r][m][h]
__device__ float g_Tu[(size_t)RR*NN*HH];    // [r][n][h]
__device__ float g_Tvt[(size_t)RR*HH*NN];   // [r][h][m]

// ---------------- pass 1: row/col sums of support --------------------------
// grid (32, 16, RR), block 128. mc: 128-col chunk of m; nc: 256-row chunk of n.
__global__ void k_sums(const float* __restrict__ supp){
  const int r = blockIdx.z, mc = blockIdx.x, nc = blockIdx.y;
  const int m0 = mc*128, n0 = nc*256;
  const int w = threadIdx.x>>5, lane = threadIdx.x&31;
  const float* base = supp + (size_t)r*NN*NN + m0 + lane*4;
  float cx=0.f, cy=0.f, cz=0.f, cw=0.f;
  float* rp = g_rowPart + ((size_t)r*32 + mc)*NN;
  #pragma unroll 4
  for(int i=0;i<64;i++){
    const int n = n0 + w*64 + i;
    const float4 v = *reinterpret_cast<const float4*>(base + (size_t)n*NN);
    float s = v.x+v.y+v.z+v.w;
    cx+=v.x; cy+=v.y; cz+=v.z; cw+=v.w;
    #pragma unroll
    for(int o=16;o;o>>=1) s += __shfl_xor_sync(0xffffffffu, s, o);
    if(lane==0) rp[n] = s;
  }
  __shared__ float sc[4][128];
  sc[w][lane*4+0]=cx; sc[w][lane*4+1]=cy; sc[w][lane*4+2]=cz; sc[w][lane*4+3]=cw;
  __syncthreads();
  if(threadIdx.x < 128){
    float s = sc[0][threadIdx.x]+sc[1][threadIdx.x]+sc[2][threadIdx.x]+sc[3][threadIdx.x];
    g_colPart[((size_t)r*16 + nc)*NN + m0 + threadIdx.x] = s;
  }
}

__global__ void k_reduce(){
  const int idx = blockIdx.x*256 + threadIdx.x;
  if(idx < RR*NN){
    const int r = idx/NN, n = idx%NN;
    float s=0.f;
    #pragma unroll
    for(int mc=0; mc<32; mc++) s += g_rowPart[((size_t)r*32+mc)*NN + n];
    g_cinv[idx] = (s>0.f)? rsqrtf(s) : 0.f;
  } else {
    const int j = idx - RR*NN;
    const int r = j/NN, m = j%NN;
    float s=0.f;
    #pragma unroll
    for(int nc=0; nc<16; nc++) s += g_colPart[((size_t)r*16+nc)*NN + m];
    g_rinv[j] = (s>0.f)? rsqrtf(s) : 0.f;
  }
}

__global__ void k_weights(const float* __restrict__ uw, const float* __restrict__ vw){
  const int i = blockIdx.x*256 + threadIdx.x;
  float au=0.f, av=0.f;
  #pragma unroll
  for(int r=0;r<RR;r++){
    au += uw[r*DD*HH + i]; g_uw[r*DD*HH + i] = au;
    av += vw[r*DD*HH + i]; g_vw[r*DD*HH + i] = av;
  }
}

// ---------------- TF32 / mma helpers ---------------------------------------
__device__ __forceinline__ unsigned f2tf(float x){
  unsigned r; asm("cvt.rna.tf32.f32 %0, %1;" : "=r"(r) : "f"(x)); return r;
}
__device__ __forceinline__ void mma8(float* c, const unsigned* a, const unsigned* b){
  asm volatile("mma.sync.aligned.m16n8k8.row.col.f32.tf32.tf32.f32 "
    "{%0,%1,%2,%3},{%4,%5,%6,%7},{%8,%9},{%0,%1,%2,%3};"
    : "+f"(c[0]),"+f"(c[1]),"+f"(c[2]),"+f"(c[3])
    : "r"(a[0]),"r"(a[1]),"r"(a[2]),"r"(a[3]),"r"(b[0]),"r"(b[1]));
}
__device__ __forceinline__ void cpa16(uint32_t dst, const void* src){
  asm volatile("cp.async.cg.shared.global [%0], [%1], 16;" :: "r"(dst), "l"(src));
}
#define CP_COMMIT asm volatile("cp.async.commit_group;" ::: "memory")
#define CP_WAIT1  asm volatile("cp.async.wait_group 1;"  ::: "memory")

// K-chunk 32 smem layout (word strides):
// A: rows x 32 words, stride 36 -> frag banks (4*l4+lc) distinct.
// B: 32 k-rows x 64/128 words, stride 72/136 (==8 mod 32) -> banks (8*lc+l4) distinct.
#define A_STR 36
#define BU_STR 72
#define BV_STR 136
#define STG_WORDS (128*A_STR + 32*BU_STR)   // 6912 words = 27648 B (z1 needs 6656)
#define STG_BYTES (STG_WORDS*4)
#define DYN_BYTES (3*STG_BYTES)             // 82944 B, occupancy 2

template<int BS>
__device__ __forceinline__ void load_frag(const unsigned* __restrict__ Ab,
                                          const unsigned* __restrict__ Bb,
                                          int wm,int wn,int l4,int lc,int k8,
                                          unsigned a[2][4], unsigned b[4][2]){
  #pragma unroll
  for(int mi=0; mi<2; mi++){
    const int rr = wm*32 + mi*16 + l4;
    a[mi][0]=Ab[rr*A_STR     + k8+lc];
    a[mi][1]=Ab[(rr+8)*A_STR + k8+lc];
    a[mi][2]=Ab[rr*A_STR     + k8+lc+4];
    a[mi][3]=Ab[(rr+8)*A_STR + k8+lc+4];
  }
  #pragma unroll
  for(int ni=0; ni<4; ni++){
    const int cc = wn*32 + ni*8 + l4;
    b[ni][0]=Bb[(k8+lc)*BS   + cc];
    b[ni][1]=Bb[(k8+lc+4)*BS + cc];
  }
}

template<int BS>
__device__ __forceinline__ void chunk_mma(const unsigned* __restrict__ Ab,
                                          const unsigned* __restrict__ Bb,
                                          int wm,int wn,int l4,int lc,
                                          float acc[2][4][4]){
  unsigned a[2][2][4], b[2][4][2];
  load_frag<BS>(Ab,Bb,wm,wn,l4,lc,0,a[0],b[0]);
  #pragma unroll
  for(int ks=0; ks<4; ks++){
    const int cur = ks&1;
    if(ks<3) load_frag<BS>(Ab,Bb,wm,wn,l4,lc,(ks+1)*8,a[cur^1],b[cur^1]);
    #pragma unroll
    for(int ni=0; ni<4; ni++){
      mma8(acc[0][ni], a[cur][0], b[cur][ni]);
      mma8(acc[1][ni], a[cur][1], b[cur][ni]);
    }
  }
}

// ---------------- k_tmp2: Xh / Y via mma (raw fp32 operands, K16) ----------
// side 0: Xh[r][h][n] = tf32( (u_feat @ cum_uw)[n][h] * cinv[r][n] )
// side 1: Y [r][m][h] = tf32( (v_feat @ cum_vw)[m][h] * rinv[r][m] )
#define TA_STR 20
__global__ __launch_bounds__(128) void k_tmp2(const float* __restrict__ uf,
                                              const float* __restrict__ vf){
  __shared__ __align__(16) unsigned smA[64*TA_STR];
  __shared__ __align__(16) unsigned smB[16*BU_STR];
  const int side = blockIdx.z, r = blockIdx.y, n0 = blockIdx.x*64;
  const int tid = threadIdx.x;
  const int wid = tid>>5, lane = tid&31, l4 = lane>>2, lc = lane&3;
  const int wm = wid&1, wn = wid>>1;
  const float* feat = (side ? vf : uf) + (size_t)n0*DD;
  const float* wgt  = (side ? g_vw : g_uw) + r*DD*HH;
  float acc[2][4][4];
  #pragma unroll
  for(int i=0;i<2;i++) for(int j=0;j<4;j++) for(int k=0;k<4;k++) acc[i][j][k]=0.f;

  for(int k0=0; k0<DD; k0+=16){
    #pragma unroll
    for(int i=0;i<2;i++){                      // A 64x16 raw
      const int f = tid + i*128, row = f>>2, c = (f&3)*4;
      *reinterpret_cast<uint4*>(smA + row*TA_STR + c) =
        *reinterpret_cast<const uint4*>(feat + (size_t)row*DD + k0 + c);
    }
    #pragma unroll
    for(int i=0;i<2;i++){                      // B 16x64 raw
      const int f = tid + i*128, row = f>>4, c = (f&15)*4;
      *reinterpret_cast<uint4*>(smB + row*BU_STR + c) =
        *reinterpret_cast<const uint4*>(wgt + (size_t)(k0+row)*HH + c);
    }
    __syncthreads();
    #pragma unroll
    for(int ks=0; ks<2; ks++){
      const int k8 = ks*8;
      unsigned a[2][4];
      #pragma unroll
      for(int mi=0; mi<2; mi++){
        const int rr = wm*32 + mi*16 + l4;
        a[mi][0]=smA[rr*TA_STR     + k8+lc];
        a[mi][1]=smA[(rr+8)*TA_STR + k8+lc];
        a[mi][2]=smA[rr*TA_STR     + k8+lc+4];
        a[mi][3]=smA[(rr+8)*TA_STR + k8+lc+4];
      }
      #pragma unroll
      for(int ni=0; ni<4; ni++){
        unsigned b[2];
        const int cc = wn*32 + ni*8 + l4;
        b[0]=smB[(k8+lc)*BU_STR   + cc];
        b[1]=smB[(k8+lc+4)*BU_STR + cc];
        mma8(acc[0][ni], a[0], b);
        mma8(acc[1][ni], a[1], b);
      }
    }
    __syncthreads();
  }
  const float* sv = (side ? g_rinv : g_cinv) + r*NN;
  #pragma unroll
  for(int mi=0; mi<2; mi++){
    const int n = n0 + wm*32 + mi*16 + l4;
    const float s0 = sv[n], s1 = sv[n+8];
    #pragma unroll
    for(int ni=0; ni<4; ni++){
      const int h = wn*32 + ni*8 + lc*2;
      if(side==0){
        g_Xh[((size_t)r*HH + h  )*NN + n  ] = __uint_as_float(f2tf(acc[mi][ni][0]*s0));
        g_Xh[((size_t)r*HH + h+1)*NN + n  ] = __uint_as_float(f2tf(acc[mi][ni][1]*s0));
        g_Xh[((size_t)r*HH + h  )*NN + n+8] = __uint_as_float(f2tf(acc[mi][ni][2]*s1));
        g_Xh[((size_t)r*HH + h+1)*NN + n+8] = __uint_as_float(f2tf(acc[mi][ni][3]*s1));
      } else {
        g_Y[((size_t)r*NN + n  )*HH + h  ] = __uint_as_float(f2tf(acc[mi][ni][0]*s0));
        g_Y[((size_t)r*NN + n  )*HH + h+1] = __uint_as_float(f2tf(acc[mi][ni][1]*s0));
        g_Y[((size_t)r*NN + n+8)*HH + h  ] = __uint_as_float(f2tf(acc[mi][ni][2]*s1));
        g_Y[((size_t)r*NN + n+8)*HH + h+1] = __uint_as_float(f2tf(acc[mi][ni][3]*s1));
      }
    }
  }
}

// ---------------- dominant kernel: dual GEMM, K32 chunks, 3-stage cp.async -
// z=0:  T_u[r][n][h]  = sum_m supp[r][n][m] * Y[r][m][h]   (CTA 128n x 64h)
// z=1:  Tvt[r][h][m]  = sum_n Xh[r][h][n] * supp[r][n][m]  (CTA 64h x 128m)
// support fed raw (HW tf32 truncation); Y/Xh pre-rounded tf32.
__global__ __launch_bounds__(256,2) void k_gemm(const float* __restrict__ supp){
  extern __shared__ __align__(16) unsigned char smbuf[];
  const int r = blockIdx.y;
  const int tid = threadIdx.x;
  const int wid = tid>>5, lane = tid&31, l4 = lane>>2, lc = lane&3;
  const uint32_t smb = (uint32_t)__cvta_generic_to_shared(smbuf);
  float acc[2][4][4];
  #pragma unroll
  for(int i=0;i<2;i++) for(int j=0;j<4;j++) for(int k=0;k<4;k++) acc[i][j][k]=0.f;

  if(blockIdx.z == 0){
    const int n0 = blockIdx.x*128;
    const int wm = wid & 3, wn = wid >> 2;          // 4x2 warp grid
    const float* A  = supp + ((size_t)r*NN + n0)*NN;
    const float* Bp = g_Y  + (size_t)r*NN*HH;
    auto load = [&](int j){
      const uint32_t sa = smb + (uint32_t)(j%3)*STG_BYTES;
      const uint32_t sb = sa + 128*A_STR*4;
      const int k0 = j*32;
      #pragma unroll
      for(int i=0;i<4;i++){                         // A 128x32
        const int f = tid + i*256, row = f>>3, c = (f&7)*4;
        cpa16(sa + (uint32_t)(row*A_STR + c)*4u, A + (size_t)row*NN + k0 + c);
      }
      #pragma unroll
      for(int i=0;i<2;i++){                         // B 32x64
        const int f = tid + i*256, row = f>>4, c = (f&15)*4;
        cpa16(sb + (uint32_t)(row*BU_STR + c)*4u, Bp + (size_t)(k0+row)*HH + c);
      }
    };
    load(0); CP_COMMIT; load(1); CP_COMMIT;
    for(int it=0; it<NN/32; it++){
      CP_WAIT1; __syncthreads();
      const unsigned* Ab = (const unsigned*)(smbuf + (it%3)*STG_BYTES);
      chunk_mma<BU_STR>(Ab, Ab + 128*A_STR, wm, wn, l4, lc, acc);
      if(it+2 < NN/32) load(it+2);
      CP_COMMIT;
    }
    float* Out = g_Tu + ((size_t)r*NN + n0)*HH;
    #pragma unroll
    for(int mi=0; mi<2; mi++){
      const int r0 = wm*32 + mi*16 + l4;
      #pragma unroll
      for(int ni=0; ni<4; ni++){
        const int h = wn*32 + ni*8 + lc*2;
        *reinterpret_cast<float2*>(&Out[(size_t)r0*HH + h])     = make_float2(acc[mi][ni][0], acc[mi][ni][1]);
        *reinterpret_cast<float2*>(&Out[(size_t)(r0+8)*HH + h]) = make_float2(acc[mi][ni][2], acc[mi][ni][3]);
      }
    }
  } else {
    const int m0 = blockIdx.x*128;
    const int wm = wid & 1, wn = wid >> 1;          // 2x4 warp grid
    const float* A  = g_Xh + (size_t)r*HH*NN;       // [h][n]
    const float* Bp = supp + (size_t)r*NN*NN + m0;  // rows n(K), cols m
    auto load = [&](int j){
      const uint32_t sa = smb + (uint32_t)(j%3)*STG_BYTES;
      const uint32_t sb = sa + 64*A_STR*4;
      const int k0 = j*32;
      #pragma unroll
      for(int i=0;i<2;i++){                         // A 64x32
        const int f = tid + i*256, row = f>>3, c = (f&7)*4;
        cpa16(sa + (uint32_t)(row*A_STR + c)*4u, A + (size_t)row*NN + k0 + c);
      }
      #pragma unroll
      for(int i=0;i<4;i++){                         // B 32x128
        const int f = tid + i*256, row = f>>5, c = (f&31)*4;
        cpa16(sb + (uint32_t)(row*BV_STR + c)*4u, Bp + (size_t)(k0+row)*NN + c);
      }
    };
    load(0); CP_COMMIT; load(1); CP_COMMIT;
    for(int it=0; it<NN/32; it++){
      CP_WAIT1; __syncthreads();
      const unsigned* Ab = (const unsigned*)(smbuf + (it%3)*STG_BYTES);
      chunk_mma<BV_STR>(Ab, Ab + 64*A_STR, wm, wn, l4, lc, acc);
      if(it+2 < NN/32) load(it+2);
      CP_COMMIT;
    }
    float* Out = g_Tvt + (size_t)r*HH*NN + m0;
    #pragma unroll
    for(int mi=0; mi<2; mi++){
      const int hr = wm*32 + mi*16 + l4;
      #pragma unroll
      for(int ni=0; ni<4; ni++){
        const int mcol = wn*32 + ni*8 + lc*2;
        *reinterpret_cast<float2*>(&Out[(size_t)hr*NN + mcol])     = make_float2(acc[mi][ni][0], acc[mi][ni][1]);
        *reinterpret_cast<float2*>(&Out[(size_t)(hr+8)*NN + mcol]) = make_float2(acc[mi][ni][2], acc[mi][ni][3]);
      }
    }
  }
}

// ---------------- gather + bias + relu -------------------------------------
__global__ void k_out(const int* __restrict__ u, const int* __restrict__ v,
                      const float* __restrict__ bias, float* __restrict__ out){
  const int b = blockIdx.x;
  const int h = threadIdx.x;  // 64
  const int ub = u[b], vb = v[b];
  float su = bias[h], sv = bias[h];
  #pragma unroll
  for(int r=0;r<RR;r++){
    su += g_cinv[r*NN + ub] * g_Tu [((size_t)r*NN + ub)*HH + h];
    sv += g_rinv[r*NN + vb] * g_Tvt[((size_t)r*HH + h)*NN + vb];
  }
  out[(size_t)b*HH + h]        = fmaxf(su, 0.f);
  out[(size_t)(BB + b)*HH + h] = fmaxf(sv, 0.f);
}

// ---------------- launch ----------------------------------------------------
extern "C" void kernel_launch(void* const* d_in, const int* in_sizes, int n_in,
                              void* d_out, int out_size){
  (void)in_sizes; (void)n_in; (void)out_size;
  const float* u_feat = (const float*)d_in[0];
  const float* v_feat = (const float*)d_in[1];
  const int*   u      = (const int*)  d_in[2];
  const int*   v      = (const int*)  d_in[3];
  const float* supp   = (const float*)d_in[4];
  const float* u_w    = (const float*)d_in[5];
  const float* v_w    = (const float*)d_in[6];
  const float* u_bias = (const float*)d_in[7];
  float* out = (float*)d_out;

  static int attr_done = 0;
  if(!attr_done){
    cudaFuncSetAttribute(k_gemm, cudaFuncAttributeMaxDynamicSharedMemorySize, DYN_BYTES);
    attr_done = 1;
  }

  k_sums   <<<dim3(32, 16, RR), 128>>>(supp);
  k_reduce <<<160, 256>>>();
  k_weights<<<64, 256>>>(u_w, v_w);
  k_tmp2   <<<dim3(64, RR, 2), 128>>>(u_feat, v_feat);
  k_gemm   <<<dim3(32, RR, 2), 256, DYN_BYTES>>>(supp);
  k_out    <<<BB, HH>>>(u, v, u_bias, out);
}

// round 12
// speedup vs baseline: 1.4929x; 1.0209x over previous
#include <cuda_runtime.h>
#include <cstdint>

#define RR 5
#define NN 4096
#define DD 256
#define HH 64
#define BB 4096

// ---------------- scratch (static device globals; no allocs allowed) -------
__device__ float g_uw[RR*DD*HH];            // cumsum(u_weight)
__device__ float g_vw[RR*DD*HH];            // cumsum(v_weight)
__device__ float g_rowPart[RR*32*NN];       // [r][mchunk][n]
__device__ float g_colPart[RR*16*NN];       // [r][nchunk][m]
__device__ float g_cinv[RR*NN];             // index n
__device__ float g_rinv[RR*NN];             // index m
__device__ float g_Xh[(size_t)RR*HH*NN];    // X^T (tf32-rounded) [r][h][n]
__device__ float g_Yt[(size_t)RR*HH*NN];    // Y^T (tf32-rounded) [r][h][m]
__device__ float g_Tu[(size_t)RR*NN*HH];    // [r][n][h]
__device__ float g_Tvt[(size_t)RR*HH*NN];   // [r][h][m]

// ---------------- pass 1: row/col sums of support --------------------------
__global__ void k_sums(const float* __restrict__ supp){
  const int r = blockIdx.z, mc = blockIdx.x, nc = blockIdx.y;
  const int m0 = mc*128, n0 = nc*256;
  const int w = threadIdx.x>>5, lane = threadIdx.x&31;
  const float* base = supp + (size_t)r*NN*NN + m0 + lane*4;
  float cx=0.f, cy=0.f, cz=0.f, cw=0.f;
  float* rp = g_rowPart + ((size_t)r*32 + mc)*NN;
  #pragma unroll 4
  for(int i=0;i<64;i++){
    const int n = n0 + w*64 + i;
    const float4 v = *reinterpret_cast<const float4*>(base + (size_t)n*NN);
    float s = v.x+v.y+v.z+v.w;
    cx+=v.x; cy+=v.y; cz+=v.z; cw+=v.w;
    #pragma unroll
    for(int o=16;o;o>>=1) s += __shfl_xor_sync(0xffffffffu, s, o);
    if(lane==0) rp[n] = s;
  }
  __shared__ float sc[4][128];
  sc[w][lane*4+0]=cx; sc[w][lane*4+1]=cy; sc[w][lane*4+2]=cz; sc[w][lane*4+3]=cw;
  __syncthreads();
  if(threadIdx.x < 128){
    float s = sc[0][threadIdx.x]+sc[1][threadIdx.x]+sc[2][threadIdx.x]+sc[3][threadIdx.x];
    g_colPart[((size_t)r*16 + nc)*NN + m0 + threadIdx.x] = s;
  }
}

__global__ void k_reduce(){
  const int idx = blockIdx.x*256 + threadIdx.x;
  if(idx < RR*NN){
    const int r = idx/NN, n = idx%NN;
    float s=0.f;
    #pragma unroll
    for(int mc=0; mc<32; mc++) s += g_rowPart[((size_t)r*32+mc)*NN + n];
    g_cinv[idx] = (s>0.f)? rsqrtf(s) : 0.f;
  } else {
    const int j = idx - RR*NN;
    const int r = j/NN, m = j%NN;
    float s=0.f;
    #pragma unroll
    for(int nc=0; nc<16; nc++) s += g_colPart[((size_t)r*16+nc)*NN + m];
    g_rinv[j] = (s>0.f)? rsqrtf(s) : 0.f;
  }
}

__global__ void k_weights(const float* __restrict__ uw, const float* __restrict__ vw){
  const int i = blockIdx.x*256 + threadIdx.x;
  float au=0.f, av=0.f;
  #pragma unroll
  for(int r=0;r<RR;r++){
    au += uw[r*DD*HH + i]; g_uw[r*DD*HH + i] = au;
    av += vw[r*DD*HH + i]; g_vw[r*DD*HH + i] = av;
  }
}

// ---------------- TF32 / mma / ldsm helpers --------------------------------
__device__ __forceinline__ unsigned f2tf(float x){
  unsigned r; asm("cvt.rna.tf32.f32 %0, %1;" : "=r"(r) : "f"(x)); return r;
}
__device__ __forceinline__ void mma8(float* c, const unsigned* a, const unsigned* b){
  asm volatile("mma.sync.aligned.m16n8k8.row.col.f32.tf32.tf32.f32 "
    "{%0,%1,%2,%3},{%4,%5,%6,%7},{%8,%9},{%0,%1,%2,%3};"
    : "+f"(c[0]),"+f"(c[1]),"+f"(c[2]),"+f"(c[3])
    : "r"(a[0]),"r"(a[1]),"r"(a[2]),"r"(a[3]),"r"(b[0]),"r"(b[1]));
}
__device__ __forceinline__ void ldsm4(unsigned* d, uint32_t addr){
  asm volatile("ldmatrix.sync.aligned.m8n8.x4.shared.b16 {%0,%1,%2,%3}, [%4];"
    : "=r"(d[0]),"=r"(d[1]),"=r"(d[2]),"=r"(d[3]) : "r"(addr));
}
__device__ __forceinline__ void cpa16(uint32_t dst, const void* src){
  asm volatile("cp.async.cg.shared.global [%0], [%1], 16;" :: "r"(dst), "l"(src));
}
#define CP_COMMIT asm volatile("cp.async.commit_group;" ::: "memory")
#define CP_WAIT1  asm volatile("cp.async.wait_group 1;"  ::: "memory")

// strides (words). A/B-tiles at 36: row*9 mod 8 distinct 16B-groups -> LDSM
// conflict-free. z1 B at 136 (==8 mod 32) -> scalar frag reads conflict-free.
#define A_STR 36
#define BT_STR 36
#define BV_STR 136
#define STG_WORDS (128*A_STR + 64*BT_STR)   // 6912 words (z1 needs 6656)
#define STG_BYTES (STG_WORDS*4)
#define DYN_BYTES (3*STG_BYTES)             // 82944 B, occupancy 2

// ---------------- k_tmp2: Xh / Yt via mma (raw fp32 operands, K16) ---------
// side 0: Xh[r][h][n] = tf32( (u_feat @ cum_uw)[n][h] * cinv[r][n] )
// side 1: Yt[r][h][m] = tf32( (v_feat @ cum_vw)[m][h] * rinv[r][m] )
#define TA_STR 20
#define TB_STR 72
__global__ __launch_bounds__(128) void k_tmp2(const float* __restrict__ uf,
                                              const float* __restrict__ vf){
  __shared__ __align__(16) unsigned smA[64*TA_STR];
  __shared__ __align__(16) unsigned smB[16*TB_STR];
  const int side = blockIdx.z, r = blockIdx.y, n0 = blockIdx.x*64;
  const int tid = threadIdx.x;
  const int wid = tid>>5, lane = tid&31, l4 = lane>>2, lc = lane&3;
  const int wm = wid&1, wn = wid>>1;
  const float* feat = (side ? vf : uf) + (size_t)n0*DD;
  const float* wgt  = (side ? g_vw : g_uw) + r*DD*HH;
  float acc[2][4][4];
  #pragma unroll
  for(int i=0;i<2;i++) for(int j=0;j<4;j++) for(int k=0;k<4;k++) acc[i][j][k]=0.f;

  for(int k0=0; k0<DD; k0+=16){
    #pragma unroll
    for(int i=0;i<2;i++){                      // A 64x16 raw
      const int f = tid + i*128, row = f>>2, c = (f&3)*4;
      *reinterpret_cast<uint4*>(smA + row*TA_STR + c) =
        *reinterpret_cast<const uint4*>(feat + (size_t)row*DD + k0 + c);
    }
    #pragma unroll
    for(int i=0;i<2;i++){                      // B 16x64 raw
      const int f = tid + i*128, row = f>>4, c = (f&15)*4;
      *reinterpret_cast<uint4*>(smB + row*TB_STR + c) =
        *reinterpret_cast<const uint4*>(wgt + (size_t)(k0+row)*HH + c);
    }
    __syncthreads();
    #pragma unroll
    for(int ks=0; ks<2; ks++){
      const int k8 = ks*8;
      unsigned a[2][4];
      #pragma unroll
      for(int mi=0; mi<2; mi++){
        const int rr = wm*32 + mi*16 + l4;
        a[mi][0]=smA[rr*TA_STR     + k8+lc];
        a[mi][1]=smA[(rr+8)*TA_STR + k8+lc];
        a[mi][2]=smA[rr*TA_STR     + k8+lc+4];
        a[mi][3]=smA[(rr+8)*TA_STR + k8+lc+4];
      }
      #pragma unroll
      for(int ni=0; ni<4; ni++){
        unsigned b[2];
        const int cc = wn*32 + ni*8 + l4;
        b[0]=smB[(k8+lc)*TB_STR   + cc];
        b[1]=smB[(k8+lc+4)*TB_STR + cc];
        mma8(acc[0][ni], a[0], b);
        mma8(acc[1][ni], a[1], b);
      }
    }
    __syncthreads();
  }
  const float* sv = (side ? g_rinv : g_cinv) + r*NN;
  float* dst = (side ? g_Yt : g_Xh) + (size_t)r*HH*NN;
  #pragma unroll
  for(int mi=0; mi<2; mi++){
    const int n = n0 + wm*32 + mi*16 + l4;
    const float s0 = sv[n], s1 = sv[n+8];
    #pragma unroll
    for(int ni=0; ni<4; ni++){
      const int h = wn*32 + ni*8 + lc*2;
      dst[(size_t)h    *NN + n  ] = __uint_as_float(f2tf(acc[mi][ni][0]*s0));
      dst[(size_t)(h+1)*NN + n  ] = __uint_as_float(f2tf(acc[mi][ni][1]*s0));
      dst[(size_t)h    *NN + n+8] = __uint_as_float(f2tf(acc[mi][ni][2]*s1));
      dst[(size_t)(h+1)*NN + n+8] = __uint_as_float(f2tf(acc[mi][ni][3]*s1));
    }
  }
}

// ---------------- dominant kernel: dual GEMM, K32, 3-stage, ldmatrix -------
// z=0:  T_u[r][n][h]  = sum_m supp[r][n][m] * Yt[r][h][m]  (CTA 128n x 64h)
// z=1:  Tvt[r][h][m]  = sum_n Xh[r][h][n] * supp[r][n][m]  (CTA 64h x 128m)
// support fed raw (HW tf32 truncation); Yt/Xh pre-rounded tf32.
__global__ __launch_bounds__(256,2) void k_gemm(const float* __restrict__ supp){
  extern __shared__ __align__(16) unsigned char smbuf[];
  const int r = blockIdx.y;
  const int tid = threadIdx.x;
  const int wid = tid>>5, lane = tid&31, l4 = lane>>2, lc = lane&3;
  const uint32_t smb = (uint32_t)__cvta_generic_to_shared(smbuf);
  // per-thread ldmatrix row/col pattern (b32 view of m8n8.b16 tiles)
  const int lrow = (lane&7) + ((lane>>3)&1)*8;   // A: row within 16-row frag
  const int lcol = (lane>>4)*4;                  // A: k-offset 0/4
  const int brow = (lane&7) + (lane>>4)*8;       // B: n-row within 16
  const int bcol = ((lane>>3)&1)*4;              // B: k-offset 0/4
  float acc[2][4][4];
  #pragma unroll
  for(int i=0;i<2;i++) for(int j=0;j<4;j++) for(int k=0;k<4;k++) acc[i][j][k]=0.f;

  if(blockIdx.z == 0){
    const int n0 = blockIdx.x*128;
    const int wm = wid & 3, wn = wid >> 2;          // 4x2 warp grid
    const float* A  = supp + ((size_t)r*NN + n0)*NN;
    const float* Bp = g_Yt + (size_t)r*HH*NN;       // [h][m]
    auto load = [&](int j){
      const uint32_t sa = smb + (uint32_t)(j%3)*STG_BYTES;
      const uint32_t sb = sa + 128*A_STR*4;
      const int k0 = j*32;
      #pragma unroll
      for(int i=0;i<4;i++){                         // A 128x32
        const int f = tid + i*256, row = f>>3, c = (f&7)*4;
        cpa16(sa + (uint32_t)(row*A_STR + c)*4u, A + (size_t)row*NN + k0 + c);
      }
      #pragma unroll
      for(int i=0;i<2;i++){                         // B 64x32 (Yt rows h)
        const int f = tid + i*256, row = f>>3, c = (f&7)*4;
        cpa16(sb + (uint32_t)(row*BT_STR + c)*4u, Bp + (size_t)row*NN + k0 + c);
      }
    };
    load(0); CP_COMMIT; load(1); CP_COMMIT;
    for(int it=0; it<NN/32; it++){
      CP_WAIT1; __syncthreads();
      const uint32_t sa = smb + (uint32_t)(it%3)*STG_BYTES;
      const uint32_t sb = sa + 128*A_STR*4;
      const uint32_t aA0 = sa + (uint32_t)((wm*32 + lrow)*A_STR + lcol)*4u;
      const uint32_t aA1 = aA0 + 16*A_STR*4;
      const uint32_t bB0 = sb + (uint32_t)((wn*32 + brow)*BT_STR + bcol)*4u;
      const uint32_t bB1 = bB0 + 16*BT_STR*4;
      #pragma unroll
      for(int k8=0; k8<32; k8+=8){
        unsigned av0[4], av1[4], bv0[4], bv1[4];
        ldsm4(av0, aA0 + k8*4); ldsm4(av1, aA1 + k8*4);
        ldsm4(bv0, bB0 + k8*4); ldsm4(bv1, bB1 + k8*4);
        mma8(acc[0][0], av0, bv0+0);
        mma8(acc[0][1], av0, bv0+2);
        mma8(acc[0][2], av0, bv1+0);
        mma8(acc[0][3], av0, bv1+2);
        mma8(acc[1][0], av1, bv0+0);
        mma8(acc[1][1], av1, bv0+2);
        mma8(acc[1][2], av1, bv1+0);
        mma8(acc[1][3], av1, bv1+2);
      }
      if(it+2 < NN/32) load(it+2);
      CP_COMMIT;
    }
    float* Out = g_Tu + ((size_t)r*NN + n0)*HH;
    #pragma unroll
    for(int mi=0; mi<2; mi++){
      const int r0 = wm*32 + mi*16 + l4;
      #pragma unroll
      for(int ni=0; ni<4; ni++){
        const int h = wn*32 + ni*8 + lc*2;
        *reinterpret_cast<float2*>(&Out[(size_t)r0*HH + h])     = make_float2(acc[mi][ni][0], acc[mi][ni][1]);
        *reinterpret_cast<float2*>(&Out[(size_t)(r0+8)*HH + h]) = make_float2(acc[mi][ni][2], acc[mi][ni][3]);
      }
    }
  } else {
    const int m0 = blockIdx.x*128;
    const int wm = wid & 1, wn = wid >> 1;          // 2x4 warp grid
    const float* A  = g_Xh + (size_t)r*HH*NN;       // [h][n]
    const float* Bp = supp + (size_t)r*NN*NN + m0;  // rows n(K), cols m
    auto load = [&](int j){
      const uint32_t sa = smb + (uint32_t)(j%3)*STG_BYTES;
      const uint32_t sb = sa + 64*A_STR*4;
      const int k0 = j*32;
      #pragma unroll
      for(int i=0;i<2;i++){                         // A 64x32
        const int f = tid + i*256, row = f>>3, c = (f&7)*4;
        cpa16(sa + (uint32_t)(row*A_STR + c)*4u, A + (size_t)row*NN + k0 + c);
      }
      #pragma unroll
      for(int i=0;i<4;i++){                         // B 32x128
        const int f = tid + i*256, row = f>>5, c = (f&31)*4;
        cpa16(sb + (uint32_t)(row*BV_STR + c)*4u, Bp + (size_t)(k0+row)*NN + c);
      }
    };
    load(0); CP_COMMIT; load(1); CP_COMMIT;
    for(int it=0; it<NN/32; it++){
      CP_WAIT1; __syncthreads();
      const uint32_t sa = smb + (uint32_t)(it%3)*STG_BYTES;
      const unsigned* Bb = (const unsigned*)(smbuf + (it%3)*STG_BYTES) + 64*A_STR;
      const uint32_t aA0 = sa + (uint32_t)((wm*32 + lrow)*A_STR + lcol)*4u;
      const uint32_t aA1 = aA0 + 16*A_STR*4;
      #pragma unroll
      for(int k8=0; k8<32; k8+=8){
        unsigned av0[4], av1[4];
        ldsm4(av0, aA0 + k8*4); ldsm4(av1, aA1 + k8*4);
        #pragma unroll
        for(int ni=0; ni<4; ni++){
          unsigned b[2];
          const int cc = wn*32 + ni*8 + l4;
          b[0]=Bb[(k8+lc)*BV_STR   + cc];
          b[1]=Bb[(k8+lc+4)*BV_STR + cc];
          mma8(acc[0][ni], av0, b);
          mma8(acc[1][ni], av1, b);
        }
      }
      if(it+2 < NN/32) load(it+2);
      CP_COMMIT;
    }
    float* Out = g_Tvt + (size_t)r*HH*NN + m0;
    #pragma unroll
    for(int mi=0; mi<2; mi++){
      const int hr = wm*32 + mi*16 + l4;
      #pragma unroll
      for(int ni=0; ni<4; ni++){
        const int mcol = wn*32 + ni*8 + lc*2;
        *reinterpret_cast<float2*>(&Out[(size_t)hr*NN + mcol])     = make_float2(acc[mi][ni][0], acc[mi][ni][1]);
        *reinterpret_cast<float2*>(&Out[(size_t)(hr+8)*NN + mcol]) = make_float2(acc[mi][ni][2], acc[mi][ni][3]);
      }
    }
  }
}

// ---------------- gather + bias + relu -------------------------------------
__global__ void k_out(const int* __restrict__ u, const int* __restrict__ v,
                      const float* __restrict__ bias, float* __restrict__ out){
  const int b = blockIdx.x;
  const int h = threadIdx.x;  // 64
  const int ub = u[b], vb = v[b];
  float su = bias[h], sv = bias[h];
  #pragma unroll
  for(int r=0;r<RR;r++){
    su += g_cinv[r*NN + ub] * g_Tu [((size_t)r*NN + ub)*HH + h];
    sv += g_rinv[r*NN + vb] * g_Tvt[((size_t)r*HH + h)*NN + vb];
  }
  out[(size_t)b*HH + h]        = fmaxf(su, 0.f);
  out[(size_t)(BB + b)*HH + h] = fmaxf(sv, 0.f);
}

// ---------------- launch ----------------------------------------------------
extern "C" void kernel_launch(void* const* d_in, const int* in_sizes, int n_in,
                              void* d_out, int out_size){
  (void)in_sizes; (void)n_in; (void)out_size;
  const float* u_feat = (const float*)d_in[0];
  const float* v_feat = (const float*)d_in[1];
  const int*   u      = (const int*)  d_in[2];
  const int*   v      = (const int*)  d_in[3];
  const float* supp   = (const float*)d_in[4];
  const float* u_w    = (const float*)d_in[5];
  const float* v_w    = (const float*)d_in[6];
  const float* u_bias = (const float*)d_in[7];
  float* out = (float*)d_out;

  static int attr_done = 0;
  if(!attr_done){
    cudaFuncSetAttribute(k_gemm, cudaFuncAttributeMaxDynamicSharedMemorySize, DYN_BYTES);
    attr_done = 1;
  }

  k_sums   <<<dim3(32, 16, RR), 128>>>(supp);
  k_reduce <<<160, 256>>>();
  k_weights<<<64, 256>>>(u_w, v_w);
  k_tmp2   <<<dim3(64, RR, 2), 128>>>(u_feat, v_feat);
  k_gemm   <<<dim3(32, RR, 2), 256, DYN_BYTES>>>(supp);
  k_out    <<<BB, HH>>>(u, v, u_bias, out);
}

// round 13
// speedup vs baseline: 1.5785x; 1.0573x over previous
#include <cuda_runtime.h>
#include <cstdint>

#define RR 5
#define NN 4096
#define DD 256
#define HH 64
#define BB 4096

// ---------------- scratch (static device globals; no allocs allowed) -------
__device__ float g_uw[RR*DD*HH];            // cumsum(u_weight)
__device__ float g_vw[RR*DD*HH];            // cumsum(v_weight)
__device__ float g_rowPart[RR*32*NN];       // [r][mchunk][n]
__device__ float g_colPart[RR*16*NN];       // [r][nchunk][m]
__device__ float g_cinv[RR*NN];             // index n
__device__ float g_rinv[RR*NN];             // index m
__device__ float g_Xh[(size_t)RR*HH*NN];    // X^T (tf32-rounded) [r][h][n]
__device__ float g_Yt[(size_t)RR*HH*NN];    // Y^T (tf32-rounded) [r][h][m]
__device__ float g_Tu[(size_t)RR*NN*HH];    // [r][n][h]
__device__ float g_Tvt[(size_t)RR*HH*NN];   // [r][h][m]

// ---------------- pass 1: row/col sums of support --------------------------
__global__ void k_sums(const float* __restrict__ supp){
  const int r = blockIdx.z, mc = blockIdx.x, nc = blockIdx.y;
  const int m0 = mc*128, n0 = nc*256;
  const int w = threadIdx.x>>5, lane = threadIdx.x&31;
  const float* base = supp + (size_t)r*NN*NN + m0 + lane*4;
  float cx=0.f, cy=0.f, cz=0.f, cw=0.f;
  float* rp = g_rowPart + ((size_t)r*32 + mc)*NN;
  #pragma unroll 4
  for(int i=0;i<64;i++){
    const int n = n0 + w*64 + i;
    const float4 v = *reinterpret_cast<const float4*>(base + (size_t)n*NN);
    float s = v.x+v.y+v.z+v.w;
    cx+=v.x; cy+=v.y; cz+=v.z; cw+=v.w;
    #pragma unroll
    for(int o=16;o;o>>=1) s += __shfl_xor_sync(0xffffffffu, s, o);
    if(lane==0) rp[n] = s;
  }
  __shared__ float sc[4][128];
  sc[w][lane*4+0]=cx; sc[w][lane*4+1]=cy; sc[w][lane*4+2]=cz; sc[w][lane*4+3]=cw;
  __syncthreads();
  if(threadIdx.x < 128){
    float s = sc[0][threadIdx.x]+sc[1][threadIdx.x]+sc[2][threadIdx.x]+sc[3][threadIdx.x];
    g_colPart[((size_t)r*16 + nc)*NN + m0 + threadIdx.x] = s;
  }
}

__global__ void k_reduce(){
  const int idx = blockIdx.x*256 + threadIdx.x;
  if(idx < RR*NN){
    const int r = idx/NN, n = idx%NN;
    float s=0.f;
    #pragma unroll
    for(int mc=0; mc<32; mc++) s += g_rowPart[((size_t)r*32+mc)*NN + n];
    g_cinv[idx] = (s>0.f)? rsqrtf(s) : 0.f;
  } else {
    const int j = idx - RR*NN;
    const int r = j/NN, m = j%NN;
    float s=0.f;
    #pragma unroll
    for(int nc=0; nc<16; nc++) s += g_colPart[((size_t)r*16+nc)*NN + m];
    g_rinv[j] = (s>0.f)? rsqrtf(s) : 0.f;
  }
}

__global__ void k_weights(const float* __restrict__ uw, const float* __restrict__ vw){
  const int i = blockIdx.x*256 + threadIdx.x;
  float au=0.f, av=0.f;
  #pragma unroll
  for(int r=0;r<RR;r++){
    au += uw[r*DD*HH + i]; g_uw[r*DD*HH + i] = au;
    av += vw[r*DD*HH + i]; g_vw[r*DD*HH + i] = av;
  }
}

// ---------------- TF32 / mma / ldsm helpers --------------------------------
__device__ __forceinline__ unsigned f2tf(float x){
  unsigned r; asm("cvt.rna.tf32.f32 %0, %1;" : "=r"(r) : "f"(x)); return r;
}
__device__ __forceinline__ void mma8(float* c, const unsigned* a, const unsigned* b){
  asm volatile("mma.sync.aligned.m16n8k8.row.col.f32.tf32.tf32.f32 "
    "{%0,%1,%2,%3},{%4,%5,%6,%7},{%8,%9},{%0,%1,%2,%3};"
    : "+f"(c[0]),"+f"(c[1]),"+f"(c[2]),"+f"(c[3])
    : "r"(a[0]),"r"(a[1]),"r"(a[2]),"r"(a[3]),"r"(b[0]),"r"(b[1]));
}
__device__ __forceinline__ void ldsm4(unsigned* d, uint32_t addr){
  asm volatile("ldmatrix.sync.aligned.m8n8.x4.shared.b16 {%0,%1,%2,%3}, [%4];"
    : "=r"(d[0]),"=r"(d[1]),"=r"(d[2]),"=r"(d[3]) : "r"(addr));
}
__device__ __forceinline__ void cpa16(uint32_t dst, const void* src){
  asm volatile("cp.async.cg.shared.global [%0], [%1], 16;" :: "r"(dst), "l"(src));
}
#define CP_COMMIT asm volatile("cp.async.commit_group;" ::: "memory")
#define CP_WAIT1  asm volatile("cp.async.wait_group 1;"  ::: "memory")

// strides (words). 36: row*9 mod 8 distinct 16B-groups -> LDSM conflict-free.
// 72 (==8 mod 32) -> scalar B-frag reads conflict-free.
#define A_STR 36
#define BT_STR 36
#define BU_STR 72
#define STG_WORDS (64*A_STR + 64*BT_STR)    // 4608 (z1: 64*36+32*72 = same)
#define STG_BYTES (STG_WORDS*4)             // 18432
#define DYN_BYTES (3*STG_BYTES)             // 55296 -> occupancy 4

// ---------------- k_tmp2: Xh / Yt via mma (raw fp32 operands, K16) ---------
// CTA: 64 n-rows x 32 h (h-half). Warp tile 32n x 16h. grid (128, RR, 2).
// side 0: Xh[r][h][n] = tf32( (u_feat @ cum_uw)[n][h] * cinv[r][n] )
// side 1: Yt[r][h][m] = tf32( (v_feat @ cum_vw)[m][h] * rinv[r][m] )
#define TA_STR 20
#define TB_STR 40
__global__ __launch_bounds__(128) void k_tmp2(const float* __restrict__ uf,
                                              const float* __restrict__ vf){
  __shared__ __align__(16) unsigned smA[64*TA_STR];
  __shared__ __align__(16) unsigned smB[16*TB_STR];
  const int side = blockIdx.z, r = blockIdx.y;
  const int n0 = (blockIdx.x>>1)*64, hh = (blockIdx.x&1)*32;
  const int tid = threadIdx.x;
  const int wid = tid>>5, lane = tid&31, l4 = lane>>2, lc = lane&3;
  const int wm = wid&1, wh = wid>>1;
  const float* feat = (side ? vf : uf) + (size_t)n0*DD;
  const float* wgt  = (side ? g_vw : g_uw) + r*DD*HH + hh;
  float acc[2][2][4];
  #pragma unroll
  for(int i=0;i<2;i++) for(int j=0;j<2;j++) for(int k=0;k<4;k++) acc[i][j][k]=0.f;

  for(int k0=0; k0<DD; k0+=16){
    #pragma unroll
    for(int i=0;i<2;i++){                      // A 64x16 raw
      const int f = tid + i*128, row = f>>2, c = (f&3)*4;
      *reinterpret_cast<uint4*>(smA + row*TA_STR + c) =
        *reinterpret_cast<const uint4*>(feat + (size_t)row*DD + k0 + c);
    }
    {                                          // B 16x32 raw
      const int row = tid>>3, c = (tid&7)*4;
      *reinterpret_cast<uint4*>(smB + row*TB_STR + c) =
        *reinterpret_cast<const uint4*>(wgt + (size_t)(k0+row)*HH + c);
    }
    __syncthreads();
    #pragma unroll
    for(int ks=0; ks<2; ks++){
      const int k8 = ks*8;
      unsigned a[2][4];
      #pragma unroll
      for(int mi=0; mi<2; mi++){
        const int rr = wm*32 + mi*16 + l4;
        a[mi][0]=smA[rr*TA_STR     + k8+lc];
        a[mi][1]=smA[(rr+8)*TA_STR + k8+lc];
        a[mi][2]=smA[rr*TA_STR     + k8+lc+4];
        a[mi][3]=smA[(rr+8)*TA_STR + k8+lc+4];
      }
      #pragma unroll
      for(int ni=0; ni<2; ni++){
        unsigned b[2];
        const int cc = wh*16 + ni*8 + l4;
        b[0]=smB[(k8+lc)*TB_STR   + cc];
        b[1]=smB[(k8+lc+4)*TB_STR + cc];
        mma8(acc[0][ni], a[0], b);
        mma8(acc[1][ni], a[1], b);
      }
    }
    __syncthreads();
  }
  const float* sv = (side ? g_rinv : g_cinv) + r*NN;
  float* dst = (side ? g_Yt : g_Xh) + (size_t)r*HH*NN;
  #pragma unroll
  for(int mi=0; mi<2; mi++){
    const int n = n0 + wm*32 + mi*16 + l4;
    const float s0 = sv[n], s1 = sv[n+8];
    #pragma unroll
    for(int ni=0; ni<2; ni++){
      const int h = hh + wh*16 + ni*8 + lc*2;
      dst[(size_t)h    *NN + n  ] = __uint_as_float(f2tf(acc[mi][ni][0]*s0));
      dst[(size_t)(h+1)*NN + n  ] = __uint_as_float(f2tf(acc[mi][ni][1]*s0));
      dst[(size_t)h    *NN + n+8] = __uint_as_float(f2tf(acc[mi][ni][2]*s1));
      dst[(size_t)(h+1)*NN + n+8] = __uint_as_float(f2tf(acc[mi][ni][3]*s1));
    }
  }
}

// ---------------- dominant kernel: dual GEMM, 64-wide tiles, occ 4 ---------
// grid (128, RR): x<64 -> z0 tile n0=x*64 ; x>=64 -> z1 tile m0=(x-64)*64
// z=0:  T_u[r][n][h]  = sum_m supp[r][n][m] * Yt[r][h][m]  (CTA 64n x 64h)
// z=1:  Tvt[r][h][m]  = sum_n Xh[r][h][n] * supp[r][n][m]  (CTA 64h x 64m)
// support fed raw (HW tf32 truncation); Yt/Xh pre-rounded tf32.
__global__ __launch_bounds__(128,4) void k_gemm(const float* __restrict__ supp){
  extern __shared__ __align__(16) unsigned char smbuf[];
  const int r = blockIdx.y;
  const int tid = threadIdx.x;
  const int wid = tid>>5, lane = tid&31, l4 = lane>>2, lc = lane&3;
  const int wm = wid&1, wn = wid>>1;              // 2x2 warp grid, 32x32 tiles
  const uint32_t smb = (uint32_t)__cvta_generic_to_shared(smbuf);
  const int lrow = (lane&7) + ((lane>>3)&1)*8;    // ldmatrix A row pattern
  const int lcol = (lane>>4)*4;
  const int brow = (lane&7) + (lane>>4)*8;        // ldmatrix B row pattern
  const int bcol = ((lane>>3)&1)*4;
  float acc[2][4][4];
  #pragma unroll
  for(int i=0;i<2;i++) for(int j=0;j<4;j++) for(int k=0;k<4;k++) acc[i][j][k]=0.f;

  if(blockIdx.x < 64){
    const int n0 = blockIdx.x*64;
    const float* A  = supp + ((size_t)r*NN + n0)*NN;
    const float* Bp = g_Yt + (size_t)r*HH*NN;     // [h][m]
    auto load = [&](int j){
      const uint32_t sa = smb + (uint32_t)(j%3)*STG_BYTES;
      const uint32_t sb = sa + 64*A_STR*4;
      const int k0 = j*32;
      #pragma unroll
      for(int i=0;i<4;i++){                       // A 64x32
        const int f = tid + i*128, row = f>>3, c = (f&7)*4;
        cpa16(sa + (uint32_t)(row*A_STR + c)*4u, A + (size_t)row*NN + k0 + c);
      }
      #pragma unroll
      for(int i=0;i<4;i++){                       // B 64x32 (Yt rows h)
        const int f = tid + i*128, row = f>>3, c = (f&7)*4;
        cpa16(sb + (uint32_t)(row*BT_STR + c)*4u, Bp + (size_t)row*NN + k0 + c);
      }
    };
    load(0); CP_COMMIT; load(1); CP_COMMIT;
    for(int it=0; it<NN/32; it++){
      CP_WAIT1; __syncthreads();
      const uint32_t sa = smb + (uint32_t)(it%3)*STG_BYTES;
      const uint32_t sb = sa + 64*A_STR*4;
      const uint32_t aA0 = sa + (uint32_t)((wm*32 + lrow)*A_STR + lcol)*4u;
      const uint32_t aA1 = aA0 + 16*A_STR*4;
      const uint32_t bB0 = sb + (uint32_t)((wn*32 + brow)*BT_STR + bcol)*4u;
      const uint32_t bB1 = bB0 + 16*BT_STR*4;
      #pragma unroll
      for(int k8=0; k8<32; k8+=8){
        unsigned av0[4], av1[4], bv0[4], bv1[4];
        ldsm4(av0, aA0 + k8*4); ldsm4(av1, aA1 + k8*4);
        ldsm4(bv0, bB0 + k8*4); ldsm4(bv1, bB1 + k8*4);
        mma8(acc[0][0], av0, bv0+0);
        mma8(acc[0][1], av0, bv0+2);
        mma8(acc[0][2], av0, bv1+0);
        mma8(acc[0][3], av0, bv1+2);
        mma8(acc[1][0], av1, bv0+0);
        mma8(acc[1][1], av1, bv0+2);
        mma8(acc[1][2], av1, bv1+0);
        mma8(acc[1][3], av1, bv1+2);
      }
      if(it+2 < NN/32) load(it+2);
      CP_COMMIT;
    }
    float* Out = g_Tu + ((size_t)r*NN + n0)*HH;
    #pragma unroll
    for(int mi=0; mi<2; mi++){
      const int r0 = wm*32 + mi*16 + l4;
      #pragma unroll
      for(int ni=0; ni<4; ni++){
        const int h = wn*32 + ni*8 + lc*2;
        *reinterpret_cast<float2*>(&Out[(size_t)r0*HH + h])     = make_float2(acc[mi][ni][0], acc[mi][ni][1]);
        *reinterpret_cast<float2*>(&Out[(size_t)(r0+8)*HH + h]) = make_float2(acc[mi][ni][2], acc[mi][ni][3]);
      }
    }
  } else {
    const int m0 = (blockIdx.x-64)*64;
    const float* A  = g_Xh + (size_t)r*HH*NN;     // [h][n]
    const float* Bp = supp + (size_t)r*NN*NN + m0;// rows n(K), cols m
    auto load = [&](int j){
      const uint32_t sa = smb + (uint32_t)(j%3)*STG_BYTES;
      const uint32_t sb = sa + 64*A_STR*4;
      const int k0 = j*32;
      #pragma unroll
      for(int i=0;i<4;i++){                       // A 64x32
        const int f = tid + i*128, row = f>>3, c = (f&7)*4;
        cpa16(sa + (uint32_t)(row*A_STR + c)*4u, A + (size_t)row*NN + k0 + c);
      }
      #pragma unroll
      for(int i=0;i<4;i++){                       // B 32x64
        const int f = tid + i*128, row = f>>4, c = (f&15)*4;
        cpa16(sb + (uint32_t)(row*BU_STR + c)*4u, Bp + (size_t)(k0+row)*NN + c);
      }
    };
    load(0); CP_COMMIT; load(1); CP_COMMIT;
    for(int it=0; it<NN/32; it++){
      CP_WAIT1; __syncthreads();
      const uint32_t sa = smb + (uint32_t)(it%3)*STG_BYTES;
      const unsigned* Bb = (const unsigned*)(smbuf + (it%3)*STG_BYTES) + 64*A_STR;
      const uint32_t aA0 = sa + (uint32_t)((wm*32 + lrow)*A_STR + lcol)*4u;
      const uint32_t aA1 = aA0 + 16*A_STR*4;
      #pragma unroll
      for(int k8=0; k8<32; k8+=8){
        unsigned av0[4], av1[4];
        ldsm4(av0, aA0 + k8*4); ldsm4(av1, aA1 + k8*4);
        #pragma unroll
        for(int ni=0; ni<4; ni++){
          unsigned b[2];
          const int cc = wn*32 + ni*8 + l4;
          b[0]=Bb[(k8+lc)*BU_STR   + cc];
          b[1]=Bb[(k8+lc+4)*BU_STR + cc];
          mma8(acc[0][ni], av0, b);
          mma8(acc[1][ni], av1, b);
        }
      }
      if(it+2 < NN/32) load(it+2);
      CP_COMMIT;
    }
    float* Out = g_Tvt + (size_t)r*HH*NN + m0;
    #pragma unroll
    for(int mi=0; mi<2; mi++){
      const int hr = wm*32 + mi*16 + l4;
      #pragma unroll
      for(int ni=0; ni<4; ni++){
        const int mcol = wn*32 + ni*8 + lc*2;
        *reinterpret_cast<float2*>(&Out[(size_t)hr*NN + mcol])     = make_float2(acc[mi][ni][0], acc[mi][ni][1]);
        *reinterpret_cast<float2*>(&Out[(size_t)(hr+8)*NN + mcol]) = make_float2(acc[mi][ni][2], acc[mi][ni][3]);
      }
    }
  }
}

// ---------------- gather + bias + relu -------------------------------------
__global__ void k_out(const int* __restrict__ u, const int* __restrict__ v,
                      const float* __restrict__ bias, float* __restrict__ out){
  const int b = blockIdx.x;
  const int h = threadIdx.x;  // 64
  const int ub = u[b], vb = v[b];
  float su = bias[h], sv = bias[h];
  #pragma unroll
  for(int r=0;r<RR;r++){
    su += g_cinv[r*NN + ub] * g_Tu [((size_t)r*NN + ub)*HH + h];
    sv += g_rinv[r*NN + vb] * g_Tvt[((size_t)r*HH + h)*NN + vb];
  }
  out[(size_t)b*HH + h]        = fmaxf(su, 0.f);
  out[(size_t)(BB + b)*HH + h] = fmaxf(sv, 0.f);
}

// ---------------- launch ----------------------------------------------------
extern "C" void kernel_launch(void* const* d_in, const int* in_sizes, int n_in,
                              void* d_out, int out_size){
  (void)in_sizes; (void)n_in; (void)out_size;
  const float* u_feat = (const float*)d_in[0];
  const float* v_feat = (const float*)d_in[1];
  const int*   u      = (const int*)  d_in[2];
  const int*   v      = (const int*)  d_in[3];
  const float* supp   = (const float*)d_in[4];
  const float* u_w    = (const float*)d_in[5];
  const float* v_w    = (const float*)d_in[6];
  const float* u_bias = (const float*)d_in[7];
  float* out = (float*)d_out;

  static int attr_done = 0;
  if(!attr_done){
    cudaFuncSetAttribute(k_gemm, cudaFuncAttributeMaxDynamicSharedMemorySize, DYN_BYTES);
    attr_done = 1;
  }

  k_sums   <<<dim3(32, 16, RR), 128>>>(supp);
  k_reduce <<<160, 256>>>();
  k_weights<<<64, 256>>>(u_w, v_w);
  k_tmp2   <<<dim3(128, RR, 2), 128>>>(u_feat, v_feat);
  k_gemm   <<<dim3(128, RR), 128, DYN_BYTES>>>(supp);
  k_out    <<<BB, HH>>>(u, v, u_bias, out);
}

// round 15
// speedup vs baseline: 1.6900x; 1.0706x over previous
#include <cuda_runtime.h>
#include <cstdint>

#define RR 5
#define NN 4096
#define DD 256
#define HH 64
#define BB 4096

// ---------------- scratch (static device globals; no allocs allowed) -------
__device__ float g_uw[RR*DD*HH];            // cumsum(u_weight)
__device__ float g_vw[RR*DD*HH];            // cumsum(v_weight)
__device__ float g_rowPart[RR*32*NN];       // [r][mchunk][n]
__device__ float g_colPart[RR*16*NN];       // [r][nchunk][m]
__device__ float g_cinv[RR*NN];             // index n
__device__ float g_rinv[RR*NN];             // index m
__device__ float g_Xh[(size_t)RR*HH*NN];    // X^T (tf32-rounded) [r][h][n]
__device__ float g_Yt[(size_t)RR*HH*NN];    // Y^T (tf32-rounded) [r][h][m]
__device__ float g_Tu[(size_t)RR*NN*HH];    // [r][n][h]
__device__ float g_Tvt[(size_t)RR*HH*NN];   // [r][h][m]

// ---------------- pass 1: row/col sums of support --------------------------
// grid (32, 16, RR), block 128. Warp: 4 rows/iter; 8-lane group per row,
// each lane 4x float4 at cols q*32 + j*4 (full 128-col coverage).
__global__ void k_sums(const float* __restrict__ supp){
  const int r = blockIdx.z, mc = blockIdx.x, nc = blockIdx.y;
  const int m0 = mc*128, n0 = nc*256;
  const int w = threadIdx.x>>5, lane = threadIdx.x&31;
  const int g = lane>>3, j = lane&7;
  const float* base = supp + (size_t)r*NN*NN + m0 + j*4;
  float4 c[4];
  #pragma unroll
  for(int q=0;q<4;q++) c[q] = make_float4(0.f,0.f,0.f,0.f);
  float* rp = g_rowPart + ((size_t)r*32 + mc)*NN;
  #pragma unroll 2
  for(int i=0;i<16;i++){
    const int n = n0 + w*64 + i*4 + g;
    const float* rowp = base + (size_t)n*NN;
    float s = 0.f;
    #pragma unroll
    for(int q=0;q<4;q++){
      const float4 v = *reinterpret_cast<const float4*>(rowp + q*32);
      s += v.x+v.y+v.z+v.w;
      c[q].x+=v.x; c[q].y+=v.y; c[q].z+=v.z; c[q].w+=v.w;
    }
    s += __shfl_xor_sync(0xffffffffu, s, 1);
    s += __shfl_xor_sync(0xffffffffu, s, 2);
    s += __shfl_xor_sync(0xffffffffu, s, 4);
    if(j==0) rp[n] = s;
  }
  __shared__ float sc[4][4][128];
  #pragma unroll
  for(int q=0;q<4;q++){
    sc[w][g][q*32+j*4+0]=c[q].x; sc[w][g][q*32+j*4+1]=c[q].y;
    sc[w][g][q*32+j*4+2]=c[q].z; sc[w][g][q*32+j*4+3]=c[q].w;
  }
  __syncthreads();
  if(threadIdx.x < 128){
    float s = 0.f;
    #pragma unroll
    for(int ww=0; ww<4; ww++)
      #pragma unroll
      for(int gg=0; gg<4; gg++) s += sc[ww][gg][threadIdx.x];
    g_colPart[((size_t)r*16 + nc)*NN + m0 + threadIdx.x] = s;
  }
}

__global__ void k_reduce(){
  const int idx = blockIdx.x*256 + threadIdx.x;
  if(idx < RR*NN){
    const int r = idx/NN, n = idx%NN;
    float s=0.f;
    #pragma unroll
    for(int mc=0; mc<32; mc++) s += g_rowPart[((size_t)r*32+mc)*NN + n];
    g_cinv[idx] = (s>0.f)? rsqrtf(s) : 0.f;
  } else {
    const int j = idx - RR*NN;
    const int r = j/NN, m = j%NN;
    float s=0.f;
    #pragma unroll
    for(int nc=0; nc<16; nc++) s += g_colPart[((size_t)r*16+nc)*NN + m];
    g_rinv[j] = (s>0.f)? rsqrtf(s) : 0.f;
  }
}

__global__ void k_weights(const float* __restrict__ uw, const float* __restrict__ vw){
  const int i = blockIdx.x*256 + threadIdx.x;
  float au=0.f, av=0.f;
  #pragma unroll
  for(int r=0;r<RR;r++){
    au += uw[r*DD*HH + i]; g_uw[r*DD*HH + i] = au;
    av += vw[r*DD*HH + i]; g_vw[r*DD*HH + i] = av;
  }
}

// ---------------- TF32 / mma / ldsm helpers --------------------------------
__device__ __forceinline__ unsigned f2tf(float x){
  unsigned r; asm("cvt.rna.tf32.f32 %0, %1;" : "=r"(r) : "f"(x)); return r;
}
__device__ __forceinline__ void mma8(float* c, const unsigned* a, const unsigned* b){
  asm volatile("mma.sync.aligned.m16n8k8.row.col.f32.tf32.tf32.f32 "
    "{%0,%1,%2,%3},{%4,%5,%6,%7},{%8,%9},{%0,%1,%2,%3};"
    : "+f"(c[0]),"+f"(c[1]),"+f"(c[2]),"+f"(c[3])
    : "r"(a[0]),"r"(a[1]),"r"(a[2]),"r"(a[3]),"r"(b[0]),"r"(b[1]));
}
__device__ __forceinline__ void ldsm4(unsigned* d, uint32_t addr){
  asm volatile("ldmatrix.sync.aligned.m8n8.x4.shared.b16 {%0,%1,%2,%3}, [%4];"
    : "=r"(d[0]),"=r"(d[1]),"=r"(d[2]),"=r"(d[3]) : "r"(addr));
}
__device__ __forceinline__ void cpa16(uint32_t dst, const void* src){
  asm volatile("cp.async.cg.shared.global [%0], [%1], 16;" :: "r"(dst), "l"(src));
}
#define CP_COMMIT asm volatile("cp.async.commit_group;" ::: "memory")
#define CP_WAIT1  asm volatile("cp.async.wait_group 1;"  ::: "memory")

// strides (words). 36: row*9 mod 8 distinct 16B-groups -> LDSM conflict-free.
// 72 (==8 mod 32) -> scalar B-frag reads conflict-free.
#define A_STR 36
#define BT_STR 36
#define BU_STR 72
#define STG_WORDS (64*A_STR + 64*BT_STR)    // 4608 (z1: 64*36+32*72 = same)
#define STG_BYTES (STG_WORDS*4)             // 18432
#define DYN_BYTES (3*STG_BYTES)             // 55296 -> occupancy 4

// ---------------- k_tmp2: Xh / Yt via mma (raw fp32 operands, K16) ---------
// CTA: 64 n-rows x 64 h. grid (64, RR, 2), 128 threads, warp tile 32x32.
// side 0: Xh[r][h][n] = tf32( (u_feat @ cum_uw)[n][h] * cinv[r][n] )
// side 1: Yt[r][h][m] = tf32( (v_feat @ cum_vw)[m][h] * rinv[r][m] )
#define TA_STR 20
#define TB_STR 72
__global__ __launch_bounds__(128) void k_tmp2(const float* __restrict__ uf,
                                              const float* __restrict__ vf){
  __shared__ __align__(16) unsigned smA[64*TA_STR];
  __shared__ __align__(16) unsigned smB[16*TB_STR];
  const int side = blockIdx.z, r = blockIdx.y, n0 = blockIdx.x*64;
  const int tid = threadIdx.x;
  const int wid = tid>>5, lane = tid&31, l4 = lane>>2, lc = lane&3;
  const int wm = wid&1, wn = wid>>1;
  const float* feat = (side ? vf : uf) + (size_t)n0*DD;
  const float* wgt  = (side ? g_vw : g_uw) + r*DD*HH;
  float acc[2][4][4];
  #pragma unroll
  for(int i=0;i<2;i++) for(int j=0;j<4;j++) for(int k=0;k<4;k++) acc[i][j][k]=0.f;

  for(int k0=0; k0<DD; k0+=16){
    #pragma unroll
    for(int i=0;i<2;i++){                      // A 64x16 raw
      const int f = tid + i*128, row = f>>2, c = (f&3)*4;
      *reinterpret_cast<uint4*>(smA + row*TA_STR + c) =
        *reinterpret_cast<const uint4*>(feat + (size_t)row*DD + k0 + c);
    }
    #pragma unroll
    for(int i=0;i<2;i++){                      // B 16x64 raw
      const int f = tid + i*128, row = f>>4, c = (f&15)*4;
      *reinterpret_cast<uint4*>(smB + row*TB_STR + c) =
        *reinterpret_cast<const uint4*>(wgt + (size_t)(k0+row)*HH + c);
    }
    __syncthreads();
    #pragma unroll
    for(int ks=0; ks<2; ks++){
      const int k8 = ks*8;
      unsigned a[2][4];
      #pragma unroll
      for(int mi=0; mi<2; mi++){
        const int rr = wm*32 + mi*16 + l4;
        a[mi][0]=smA[rr*TA_STR     + k8+lc];
        a[mi][1]=smA[(rr+8)*TA_STR + k8+lc];
        a[mi][2]=smA[rr*TA_STR     + k8+lc+4];
        a[mi][3]=smA[(rr+8)*TA_STR + k8+lc+4];
      }
      #pragma unroll
      for(int ni=0; ni<4; ni++){
        unsigned b[2];
        const int cc = wn*32 + ni*8 + l4;
        b[0]=smB[(k8+lc)*TB_STR   + cc];
        b[1]=smB[(k8+lc+4)*TB_STR + cc];
        mma8(acc[0][ni], a[0], b);
        mma8(acc[1][ni], a[1], b);
      }
    }
    __syncthreads();
  }
  const float* sv = (side ? g_rinv : g_cinv) + r*NN;
  float* dst = (side ? g_Yt : g_Xh) + (size_t)r*HH*NN;
  #pragma unroll
  for(int mi=0; mi<2; mi++){
    const int n = n0 + wm*32 + mi*16 + l4;
    const float s0 = sv[n], s1 = sv[n+8];
    #pragma unroll
    for(int ni=0; ni<4; ni++){
      const int h = wn*32 + ni*8 + lc*2;
      dst[(size_t)h    *NN + n  ] = __uint_as_float(f2tf(acc[mi][ni][0]*s0));
      dst[(size_t)(h+1)*NN + n  ] = __uint_as_float(f2tf(acc[mi][ni][1]*s0));
      dst[(size_t)h    *NN + n+8] = __uint_as_float(f2tf(acc[mi][ni][2]*s1));
      dst[(size_t)(h+1)*NN + n+8] = __uint_as_float(f2tf(acc[mi][ni][3]*s1));
    }
  }
}

// ---------------- dominant kernel: dual GEMM, 64-wide tiles, occ 4 ---------
// grid (128, RR): x<64 -> z0 tile n0=x*64 ; x>=64 -> z1 tile m0=(x-64)*64
// z=0:  T_u[r][n][h]  = sum_m supp[r][n][m] * Yt[r][h][m]  (CTA 64n x 64h)
// z=1:  Tvt[r][h][m]  = sum_n Xh[r][h][n] * supp[r][n][m]  (CTA 64h x 64m)
// support fed raw (HW tf32 truncation); Yt/Xh pre-rounded tf32.
__global__ __launch_bounds__(128,4) void k_gemm(const float* __restrict__ supp){
  extern __shared__ __align__(16) unsigned char smbuf[];
  const int r = blockIdx.y;
  const int tid = threadIdx.x;
  const int wid = tid>>5, lane = tid&31, l4 = lane>>2, lc = lane&3;
  const int wm = wid&1, wn = wid>>1;              // 2x2 warp grid, 32x32 tiles
  const uint32_t smb = (uint32_t)__cvta_generic_to_shared(smbuf);
  const int lrow = (lane&7) + ((lane>>3)&1)*8;    // ldmatrix A row pattern
  const int lcol = (lane>>4)*4;
  const int brow = (lane&7) + (lane>>4)*8;        // ldmatrix B row pattern
  const int bcol = ((lane>>3)&1)*4;
  float acc[2][4][4];
  #pragma unroll
  for(int i=0;i<2;i++) for(int j=0;j<4;j++) for(int k=0;k<4;k++) acc[i][j][k]=0.f;

  if(blockIdx.x < 64){
    const int n0 = blockIdx.x*64;
    const float* A  = supp + ((size_t)r*NN + n0)*NN;
    const float* Bp = g_Yt + (size_t)r*HH*NN;     // [h][m]
    auto load = [&](int j){
      const uint32_t sa = smb + (uint32_t)(j%3)*STG_BYTES;
      const uint32_t sb = sa + 64*A_STR*4;
      const int k0 = j*32;
      #pragma unroll
      for(int i=0;i<4;i++){                       // A 64x32
        const int f = tid + i*128, row = f>>3, c = (f&7)*4;
        cpa16(sa + (uint32_t)(row*A_STR + c)*4u, A + (size_t)row*NN + k0 + c);
      }
      #pragma unroll
      for(int i=0;i<4;i++){                       // B 64x32 (Yt rows h)
        const int f = tid + i*128, row = f>>3, c = (f&7)*4;
        cpa16(sb + (uint32_t)(row*BT_STR + c)*4u, Bp + (size_t)row*NN + k0 + c);
      }
    };
    load(0); CP_COMMIT; load(1); CP_COMMIT;
    for(int it=0; it<NN/32; it++){
      CP_WAIT1; __syncthreads();
      const uint32_t sa = smb + (uint32_t)(it%3)*STG_BYTES;
      const uint32_t sb = sa + 64*A_STR*4;
      const uint32_t aA0 = sa + (uint32_t)((wm*32 + lrow)*A_STR + lcol)*4u;
      const uint32_t aA1 = aA0 + 16*A_STR*4;
      const uint32_t bB0 = sb + (uint32_t)((wn*32 + brow)*BT_STR + bcol)*4u;
      const uint32_t bB1 = bB0 + 16*BT_STR*4;
      #pragma unroll
      for(int k8=0; k8<32; k8+=8){
        unsigned av0[4], av1[4], bv0[4], bv1[4];
        ldsm4(av0, aA0 + k8*4); ldsm4(av1, aA1 + k8*4);
        ldsm4(bv0, bB0 + k8*4); ldsm4(bv1, bB1 + k8*4);
        mma8(acc[0][0], av0, bv0+0);
        mma8(acc[0][1], av0, bv0+2);
        mma8(acc[0][2], av0, bv1+0);
        mma8(acc[0][3], av0, bv1+2);
        mma8(acc[1][0], av1, bv0+0);
        mma8(acc[1][1], av1, bv0+2);
        mma8(acc[1][2], av1, bv1+0);
        mma8(acc[1][3], av1, bv1+2);
      }
      if(it+2 < NN/32) load(it+2);
      CP_COMMIT;
    }
    float* Out = g_Tu + ((size_t)r*NN + n0)*HH;
    #pragma unroll
    for(int mi=0; mi<2; mi++){
      const int r0 = wm*32 + mi*16 + l4;
      #pragma unroll
      for(int ni=0; ni<4; ni++){
        const int h = wn*32 + ni*8 + lc*2;
        *reinterpret_cast<float2*>(&Out[(size_t)r0*HH + h])     = make_float2(acc[mi][ni][0], acc[mi][ni][1]);
        *reinterpret_cast<float2*>(&Out[(size_t)(r0+8)*HH + h]) = make_float2(acc[mi][ni][2], acc[mi][ni][3]);
      }
    }
  } else {
    const int m0 = (blockIdx.x-64)*64;
    const float* A  = g_Xh + (size_t)r*HH*NN;     // [h][n]
    const float* Bp = supp + (size_t)r*NN*NN + m0;// rows n(K), cols m
    auto load = [&](int j){
      const uint32_t sa = smb + (uint32_t)(j%3)*STG_BYTES;
      const uint32_t sb = sa + 64*A_STR*4;
      const int k0 = j*32;
      #pragma unroll
      for(int i=0;i<4;i++){                       // A 64x32
        const int f = tid + i*128, row = f>>3, c = (f&7)*4;
        cpa16(sa + (uint32_t)(row*A_STR + c)*4u, A + (size_t)row*NN + k0 + c);
      }
      #pragma unroll
      for(int i=0;i<4;i++){                       // B 32x64
        const int f = tid + i*128, row = f>>4, c = (f&15)*4;
        cpa16(sb + (uint32_t)(row*BU_STR + c)*4u, Bp + (size_t)(k0+row)*NN + c);
      }
    };
    load(0); CP_COMMIT; load(1); CP_COMMIT;
    for(int it=0; it<NN/32; it++){
      CP_WAIT1; __syncthreads();
      const uint32_t sa = smb + (uint32_t)(it%3)*STG_BYTES;
      const unsigned* Bb = (const unsigned*)(smbuf + (it%3)*STG_BYTES) + 64*A_STR;
      const uint32_t aA0 = sa + (uint32_t)((wm*32 + lrow)*A_STR + lcol)*4u;
      const uint32_t aA1 = aA0 + 16*A_STR*4;
      #pragma unroll
      for(int k8=0; k8<32; k8+=8){
        unsigned av0[4], av1[4];
        ldsm4(av0, aA0 + k8*4); ldsm4(av1, aA1 + k8*4);
        #pragma unroll
        for(int ni=0; ni<4; ni++){
          unsigned b[2];
          const int cc = wn*32 + ni*8 + l4;
          b[0]=Bb[(k8+lc)*BU_STR   + cc];
          b[1]=Bb[(k8+lc+4)*BU_STR + cc];
          mma8(acc[0][ni], av0, b);
          mma8(acc[1][ni], av1, b);
        }
      }
      if(it+2 < NN/32) load(it+2);
      CP_COMMIT;
    }
    float* Out = g_Tvt + (size_t)r*HH*NN + m0;
    #pragma unroll
    for(int mi=0; mi<2; mi++){
      const int hr = wm*32 + mi*16 + l4;
      #pragma unroll
      for(int ni=0; ni<4; ni++){
        const int mcol = wn*32 + ni*8 + lc*2;
        *reinterpret_cast<float2*>(&Out[(size_t)hr*NN + mcol])     = make_float2(acc[mi][ni][0], acc[mi][ni][1]);
        *reinterpret_cast<float2*>(&Out[(size_t)(hr+8)*NN + mcol]) = make_float2(acc[mi][ni][2], acc[mi][ni][3]);
      }
    }
  }
}

// ---------------- gather + bias + relu -------------------------------------
__global__ void k_out(const int* __restrict__ u, const int* __restrict__ v,
                      const float* __restrict__ bias, float* __restrict__ out){
  const int b = blockIdx.x;
  const int h = threadIdx.x;  // 64
  const int ub = u[b], vb = v[b];
  float su = bias[h], sv = bias[h];
  #pragma unroll
  for(int r=0;r<RR;r++){
    su += g_cinv[r*NN + ub] * g_Tu [((size_t)r*NN + ub)*HH + h];
    sv += g_rinv[r*NN + vb] * g_Tvt[((size_t)r*HH + h)*NN + vb];
  }
  out[(size_t)b*HH + h]        = fmaxf(su, 0.f);
  out[(size_t)(BB + b)*HH + h] = fmaxf(sv, 0.f);
}

// ---------------- launch ----------------------------------------------------
extern "C" void kernel_launch(void* const* d_in, const int* in_sizes, int n_in,
                              void* d_out, int out_size){
  (void)in_sizes; (void)n_in; (void)out_size;
  const float* u_feat = (const float*)d_in[0];
  const float* v_feat = (const float*)d_in[1];
  const int*   u      = (const int*)  d_in[2];
  const int*   v      = (const int*)  d_in[3];
  const float* supp   = (const float*)d_in[4];
  const float* u_w    = (const float*)d_in[5];
  const float* v_w    = (const float*)d_in[6];
  const float* u_bias = (const float*)d_in[7];
  float* out = (float*)d_out;

  static int attr_done = 0;
  if(!attr_done){
    cudaFuncSetAttribute(k_gemm, cudaFuncAttributeMaxDynamicSharedMemorySize, DYN_BYTES);
    attr_done = 1;
  }

  k_sums   <<<dim3(32, 16, RR), 128>>>(supp);
  k_reduce <<<160, 256>>>();
  k_weights<<<64, 256>>>(u_w, v_w);
  k_tmp2   <<<dim3(64, RR, 2), 128>>>(u_feat, v_feat);
  k_gemm   <<<dim3(128, RR), 128, DYN_BYTES>>>(supp);
  k_out    <<<BB, HH>>>(u, v, u_bias, out);
}

// round 16
// speedup vs baseline: 2.1979x; 1.3005x over previous
#include <cuda_runtime.h>
#include <cuda_fp16.h>
#include <cstdint>

#define RR 5
#define NN 4096
#define DD 256
#define HH 64
#define BB 4096

// ---------------- scratch (static device globals; no allocs allowed) -------
__device__ float  g_uw[RR*DD*HH];            // cumsum(u_weight)
__device__ float  g_vw[RR*DD*HH];            // cumsum(v_weight)
__device__ float  g_rowPart[RR*32*NN];       // [r][mchunk][n]
__device__ float  g_colPart[RR*16*NN];       // [r][nchunk][m]
__device__ float  g_cinv[RR*NN];             // index n
__device__ float  g_rinv[RR*NN];             // index m
__device__ __half g_s16[(size_t)RR*NN*NN];   // fp16 copy of support
__device__ __half g_Xh[(size_t)RR*HH*NN];    // X^T fp16 [r][h][n]
__device__ __half g_Yt[(size_t)RR*HH*NN];    // Y^T fp16 [r][h][m]
__device__ float  g_Tu[(size_t)RR*NN*HH];    // [r][n][h]
__device__ float  g_Tvt[(size_t)RR*HH*NN];   // [r][h][m]

// ---------------- pass 1: row/col sums + fp16 conversion -------------------
// grid (32, 16, RR), block 128. Warp: 4 rows/iter; 8-lane group per row,
// each lane 4x float4 at cols q*32 + j*4 (full 128-col coverage).
__global__ void k_sums(const float* __restrict__ supp){
  const int r = blockIdx.z, mc = blockIdx.x, nc = blockIdx.y;
  const int m0 = mc*128, n0 = nc*256;
  const int w = threadIdx.x>>5, lane = threadIdx.x&31;
  const int g = lane>>3, j = lane&7;
  const float* base = supp + (size_t)r*NN*NN + m0 + j*4;
  __half* s16base = g_s16 + (size_t)r*NN*NN + m0 + j*4;
  float4 c[4];
  #pragma unroll
  for(int q=0;q<4;q++) c[q] = make_float4(0.f,0.f,0.f,0.f);
  float* rp = g_rowPart + ((size_t)r*32 + mc)*NN;
  #pragma unroll 2
  for(int i=0;i<16;i++){
    const int n = n0 + w*64 + i*4 + g;
    const float* rowp = base + (size_t)n*NN;
    __half* s16row = s16base + (size_t)n*NN;
    float s = 0.f;
    #pragma unroll
    for(int q=0;q<4;q++){
      const float4 v = *reinterpret_cast<const float4*>(rowp + q*32);
      s += v.x+v.y+v.z+v.w;
      c[q].x+=v.x; c[q].y+=v.y; c[q].z+=v.z; c[q].w+=v.w;
      __half2 h01 = __floats2half2_rn(v.x, v.y);
      __half2 h23 = __floats2half2_rn(v.z, v.w);
      uint2 pk;
      pk.x = *reinterpret_cast<unsigned*>(&h01);
      pk.y = *reinterpret_cast<unsigned*>(&h23);
      *reinterpret_cast<uint2*>(s16row + q*32) = pk;
    }
    s += __shfl_xor_sync(0xffffffffu, s, 1);
    s += __shfl_xor_sync(0xffffffffu, s, 2);
    s += __shfl_xor_sync(0xffffffffu, s, 4);
    if(j==0) rp[n] = s;
  }
  __shared__ float sc[4][4][128];
  #pragma unroll
  for(int q=0;q<4;q++){
    sc[w][g][q*32+j*4+0]=c[q].x; sc[w][g][q*32+j*4+1]=c[q].y;
    sc[w][g][q*32+j*4+2]=c[q].z; sc[w][g][q*32+j*4+3]=c[q].w;
  }
  __syncthreads();
  if(threadIdx.x < 128){
    float s = 0.f;
    #pragma unroll
    for(int ww=0; ww<4; ww++)
      #pragma unroll
      for(int gg=0; gg<4; gg++) s += sc[ww][gg][threadIdx.x];
    g_colPart[((size_t)r*16 + nc)*NN + m0 + threadIdx.x] = s;
  }
}

__global__ void k_reduce(){
  const int idx = blockIdx.x*256 + threadIdx.x;
  if(idx < RR*NN){
    const int r = idx/NN, n = idx%NN;
    float s=0.f;
    #pragma unroll
    for(int mc=0; mc<32; mc++) s += g_rowPart[((size_t)r*32+mc)*NN + n];
    g_cinv[idx] = (s>0.f)? rsqrtf(s) : 0.f;
  } else {
    const int j = idx - RR*NN;
    const int r = j/NN, m = j%NN;
    float s=0.f;
    #pragma unroll
    for(int nc=0; nc<16; nc++) s += g_colPart[((size_t)r*16+nc)*NN + m];
    g_rinv[j] = (s>0.f)? rsqrtf(s) : 0.f;
  }
}

__global__ void k_weights(const float* __restrict__ uw, const float* __restrict__ vw){
  const int i = blockIdx.x*256 + threadIdx.x;
  float au=0.f, av=0.f;
  #pragma unroll
  for(int r=0;r<RR;r++){
    au += uw[r*DD*HH + i]; g_uw[r*DD*HH + i] = au;
    av += vw[r*DD*HH + i]; g_vw[r*DD*HH + i] = av;
  }
}

// ---------------- mma / ldsm helpers ---------------------------------------
__device__ __forceinline__ void mma8(float* c, const unsigned* a, const unsigned* b){
  asm volatile("mma.sync.aligned.m16n8k8.row.col.f32.tf32.tf32.f32 "
    "{%0,%1,%2,%3},{%4,%5,%6,%7},{%8,%9},{%0,%1,%2,%3};"
    : "+f"(c[0]),"+f"(c[1]),"+f"(c[2]),"+f"(c[3])
    : "r"(a[0]),"r"(a[1]),"r"(a[2]),"r"(a[3]),"r"(b[0]),"r"(b[1]));
}
__device__ __forceinline__ void mma16(float* c, const unsigned* a, const unsigned* b){
  asm volatile("mma.sync.aligned.m16n8k16.row.col.f32.f16.f16.f32 "
    "{%0,%1,%2,%3},{%4,%5,%6,%7},{%8,%9},{%0,%1,%2,%3};"
    : "+f"(c[0]),"+f"(c[1]),"+f"(c[2]),"+f"(c[3])
    : "r"(a[0]),"r"(a[1]),"r"(a[2]),"r"(a[3]),"r"(b[0]),"r"(b[1]));
}
__device__ __forceinline__ void ldsm4(unsigned* d, uint32_t addr){
  asm volatile("ldmatrix.sync.aligned.m8n8.x4.shared.b16 {%0,%1,%2,%3}, [%4];"
    : "=r"(d[0]),"=r"(d[1]),"=r"(d[2]),"=r"(d[3]) : "r"(addr));
}
__device__ __forceinline__ void ldsm4t(unsigned* d, uint32_t addr){
  asm volatile("ldmatrix.sync.aligned.m8n8.x4.trans.shared.b16 {%0,%1,%2,%3}, [%4];"
    : "=r"(d[0]),"=r"(d[1]),"=r"(d[2]),"=r"(d[3]) : "r"(addr));
}
__device__ __forceinline__ void cpa16(uint32_t dst, const void* src){
  asm volatile("cp.async.cg.shared.global [%0], [%1], 16;" :: "r"(dst), "l"(src));
}
#define CP_COMMIT asm volatile("cp.async.commit_group;" ::: "memory")
#define CP_WAIT1  asm volatile("cp.async.wait_group 1;"  ::: "memory")

// fp16 stage: K-chunk 64. A 64 rows x 72 halves (144B stride: 9 x 16B groups
// mod 8 distinct -> LDSM conflict-free), B same. Stage 18432B, 3 stages, occ 4.
#define AH_STR 72
#define STG_BYTES (64*AH_STR*2*2)           // 18432
#define DYN_BYTES (3*STG_BYTES)             // 55296 -> occupancy 4

// ---------------- k_tmp2: Xh / Yt via tf32 mma (raw fp32 in, fp16 out) -----
// CTA: 64 n-rows x 64 h. grid (64, RR, 2), 128 threads, warp tile 32x32.
// side 0: Xh[r][h][n] = fp16( (u_feat @ cum_uw)[n][h] * cinv[r][n] )
// side 1: Yt[r][h][m] = fp16( (v_feat @ cum_vw)[m][h] * rinv[r][m] )
#define TA_STR 20
#define TB_STR 72
__global__ __launch_bounds__(128) void k_tmp2(const float* __restrict__ uf,
                                              const float* __restrict__ vf){
  __shared__ __align__(16) unsigned smA[64*TA_STR];
  __shared__ __align__(16) unsigned smB[16*TB_STR];
  const int side = blockIdx.z, r = blockIdx.y, n0 = blockIdx.x*64;
  const int tid = threadIdx.x;
  const int wid = tid>>5, lane = tid&31, l4 = lane>>2, lc = lane&3;
  const int wm = wid&1, wn = wid>>1;
  const float* feat = (side ? vf : uf) + (size_t)n0*DD;
  const float* wgt  = (side ? g_vw : g_uw) + r*DD*HH;
  float acc[2][4][4];
  #pragma unroll
  for(int i=0;i<2;i++) for(int j=0;j<4;j++) for(int k=0;k<4;k++) acc[i][j][k]=0.f;

  for(int k0=0; k0<DD; k0+=16){
    #pragma unroll
    for(int i=0;i<2;i++){                      // A 64x16 raw
      const int f = tid + i*128, row = f>>2, c = (f&3)*4;
      *reinterpret_cast<uint4*>(smA + row*TA_STR + c) =
        *reinterpret_cast<const uint4*>(feat + (size_t)row*DD + k0 + c);
    }
    #pragma unroll
    for(int i=0;i<2;i++){                      // B 16x64 raw
      const int f = tid + i*128, row = f>>4, c = (f&15)*4;
      *reinterpret_cast<uint4*>(smB + row*TB_STR + c) =
        *reinterpret_cast<const uint4*>(wgt + (size_t)(k0+row)*HH + c);
    }
    __syncthreads();
    #pragma unroll
    for(int ks=0; ks<2; ks++){
      const int k8 = ks*8;
      unsigned a[2][4];
      #pragma unroll
      for(int mi=0; mi<2; mi++){
        const int rr = wm*32 + mi*16 + l4;
        a[mi][0]=smA[rr*TA_STR     + k8+lc];
        a[mi][1]=smA[(rr+8)*TA_STR + k8+lc];
        a[mi][2]=smA[rr*TA_STR     + k8+lc+4];
        a[mi][3]=smA[(rr+8)*TA_STR + k8+lc+4];
      }
      #pragma unroll
      for(int ni=0; ni<4; ni++){
        unsigned b[2];
        const int cc = wn*32 + ni*8 + l4;
        b[0]=smB[(k8+lc)*TB_STR   + cc];
        b[1]=smB[(k8+lc+4)*TB_STR + cc];
        mma8(acc[0][ni], a[0], b);
        mma8(acc[1][ni], a[1], b);
      }
    }
    __syncthreads();
  }
  const float* sv = (side ? g_rinv : g_cinv) + r*NN;
  __half* dst = (side ? g_Yt : g_Xh) + (size_t)r*HH*NN;
  #pragma unroll
  for(int mi=0; mi<2; mi++){
    const int n = n0 + wm*32 + mi*16 + l4;
    const float s0 = sv[n], s1 = sv[n+8];
    #pragma unroll
    for(int ni=0; ni<4; ni++){
      const int h = wn*32 + ni*8 + lc*2;
      dst[(size_t)h    *NN + n  ] = __float2half_rn(acc[mi][ni][0]*s0);
      dst[(size_t)(h+1)*NN + n  ] = __float2half_rn(acc[mi][ni][1]*s0);
      dst[(size_t)h    *NN + n+8] = __float2half_rn(acc[mi][ni][2]*s1);
      dst[(size_t)(h+1)*NN + n+8] = __float2half_rn(acc[mi][ni][3]*s1);
    }
  }
}

// ---------------- dominant kernel: fp16 dual GEMM, K64, occ 4 --------------
// grid (128, RR): x<64 -> z0 tile n0=x*64 ; x>=64 -> z1 tile m0=(x-64)*64
// z=0:  T_u[r][n][h]  = sum_m s16[r][n][m] * Yt[r][h][m]  (CTA 64n x 64h)
// z=1:  Tvt[r][h][m]  = sum_n Xh[r][h][n] * s16[r][n][m]  (CTA 64h x 64m)
__global__ __launch_bounds__(128,4) void k_gemm(){
  extern __shared__ __align__(16) unsigned char smbuf[];
  const int r = blockIdx.y;
  const int tid = threadIdx.x;
  const int wid = tid>>5, lane = tid&31, l4 = lane>>2, lc = lane&3;
  const int wm = wid&1, wn = wid>>1;              // 2x2 warp grid, 32x32 tiles
  const uint32_t smb = (uint32_t)__cvta_generic_to_shared(smbuf);
  const int lrow = (lane&7) + ((lane>>3)&1)*8;    // A-pattern rows (also z1-B k)
  const int lcolB = (lane>>4)*16;                 // A-pattern 16B col (k8 / n8)
  const int brow = (lane&7) + (lane>>4)*8;        // B-pattern rows (n)
  const int bcolB = ((lane>>3)&1)*16;             // B-pattern 16B col (k8)
  float acc[2][4][4];
  #pragma unroll
  for(int i=0;i<2;i++) for(int j=0;j<4;j++) for(int k=0;k<4;k++) acc[i][j][k]=0.f;

  if(blockIdx.x < 64){
    const int n0 = blockIdx.x*64;
    const __half* A  = g_s16 + ((size_t)r*NN + n0)*NN;
    const __half* Bp = g_Yt + (size_t)r*HH*NN;    // [h][m]
    auto load = [&](int j){
      const uint32_t sa = smb + (uint32_t)(j%3)*STG_BYTES;
      const uint32_t sb = sa + 64*AH_STR*2;
      const int k0 = j*64;
      #pragma unroll
      for(int i=0;i<4;i++){                       // A 64 rows x 128B
        const int f = tid + i*128, row = f>>3, c = f&7;
        cpa16(sa + (uint32_t)(row*AH_STR*2 + c*16), A + (size_t)row*NN + k0 + c*8);
      }
      #pragma unroll
      for(int i=0;i<4;i++){                       // B 64 h-rows x 128B
        const int f = tid + i*128, row = f>>3, c = f&7;
        cpa16(sb + (uint32_t)(row*AH_STR*2 + c*16), Bp + (size_t)row*NN + k0 + c*8);
      }
    };
    load(0); CP_COMMIT; load(1); CP_COMMIT;
    for(int it=0; it<NN/64; it++){
      CP_WAIT1; __syncthreads();
      const uint32_t sa = smb + (uint32_t)(it%3)*STG_BYTES;
      const uint32_t sb = sa + 64*AH_STR*2;
      const uint32_t aA0 = sa + (uint32_t)((wm*32 + lrow)*AH_STR*2) + lcolB;
      const uint32_t aA1 = aA0 + 16*AH_STR*2;
      const uint32_t bB0 = sb + (uint32_t)((wn*32 + brow)*AH_STR*2) + bcolB;
      const uint32_t bB1 = bB0 + 16*AH_STR*2;
      #pragma unroll
      for(int k16=0; k16<4; k16++){
        unsigned av0[4], av1[4], bv0[4], bv1[4];
        ldsm4(av0, aA0 + k16*32); ldsm4(av1, aA1 + k16*32);
        ldsm4(bv0, bB0 + k16*32); ldsm4(bv1, bB1 + k16*32);
        mma16(acc[0][0], av0, bv0+0);
        mma16(acc[0][1], av0, bv0+2);
        mma16(acc[0][2], av0, bv1+0);
        mma16(acc[0][3], av0, bv1+2);
        mma16(acc[1][0], av1, bv0+0);
        mma16(acc[1][1], av1, bv0+2);
        mma16(acc[1][2], av1, bv1+0);
        mma16(acc[1][3], av1, bv1+2);
      }
      if(it+2 < NN/64) load(it+2);
      CP_COMMIT;
    }
    float* Out = g_Tu + ((size_t)r*NN + n0)*HH;
    #pragma unroll
    for(int mi=0; mi<2; mi++){
      const int r0 = wm*32 + mi*16 + l4;
      #pragma unroll
      for(int ni=0; ni<4; ni++){
        const int h = wn*32 + ni*8 + lc*2;
        *reinterpret_cast<float2*>(&Out[(size_t)r0*HH + h])     = make_float2(acc[mi][ni][0], acc[mi][ni][1]);
        *reinterpret_cast<float2*>(&Out[(size_t)(r0+8)*HH + h]) = make_float2(acc[mi][ni][2], acc[mi][ni][3]);
      }
    }
  } else {
    const int m0 = (blockIdx.x-64)*64;
    const __half* A  = g_Xh + (size_t)r*HH*NN;    // [h][n]
    const __half* Bp = g_s16 + (size_t)r*NN*NN + m0; // rows n(K), cols m
    auto load = [&](int j){
      const uint32_t sa = smb + (uint32_t)(j%3)*STG_BYTES;
      const uint32_t sb = sa + 64*AH_STR*2;
      const int k0 = j*64;
      #pragma unroll
      for(int i=0;i<4;i++){                       // A 64 h-rows x 128B
        const int f = tid + i*128, row = f>>3, c = f&7;
        cpa16(sa + (uint32_t)(row*AH_STR*2 + c*16), A + (size_t)row*NN + k0 + c*8);
      }
      #pragma unroll
      for(int i=0;i<4;i++){                       // B 64 k-rows x 128B
        const int f = tid + i*128, row = f>>3, c = f&7;
        cpa16(sb + (uint32_t)(row*AH_STR*2 + c*16), Bp + (size_t)(k0+row)*NN + c*8);
      }
    };
    load(0); CP_COMMIT; load(1); CP_COMMIT;
    for(int it=0; it<NN/64; it++){
      CP_WAIT1; __syncthreads();
      const uint32_t sa = smb + (uint32_t)(it%3)*STG_BYTES;
      const uint32_t sb = sa + 64*AH_STR*2;
      const uint32_t aA0 = sa + (uint32_t)((wm*32 + lrow)*AH_STR*2) + lcolB;
      const uint32_t aA1 = aA0 + 16*AH_STR*2;
      // z1 B: [k rows][n cols], trans-ldmatrix. Rows use lrow (k), cols lcolB (n8).
      const uint32_t bT = sb + (uint32_t)(lrow*AH_STR*2) + (uint32_t)(wn*32*2) + lcolB;
      #pragma unroll
      for(int k16=0; k16<4; k16++){
        unsigned av0[4], av1[4], bv0[4], bv1[4];
        ldsm4(av0, aA0 + k16*32); ldsm4(av1, aA1 + k16*32);
        ldsm4t(bv0, bT + (uint32_t)(k16*16*AH_STR*2));       // n0-15
        ldsm4t(bv1, bT + (uint32_t)(k16*16*AH_STR*2) + 32);  // n16-31
        mma16(acc[0][0], av0, bv0+0);
        mma16(acc[0][1], av0, bv0+2);
        mma16(acc[0][2], av0, bv1+0);
        mma16(acc[0][3], av0, bv1+2);
        mma16(acc[1][0], av1, bv0+0);
        mma16(acc[1][1], av1, bv0+2);
        mma16(acc[1][2], av1, bv1+0);
        mma16(acc[1][3], av1, bv1+2);
      }
      if(it+2 < NN/64) load(it+2);
      CP_COMMIT;
    }
    float* Out = g_Tvt + (size_t)r*HH*NN + m0;
    #pragma unroll
    for(int mi=0; mi<2; mi++){
      const int hr = wm*32 + mi*16 + l4;
      #pragma unroll
      for(int ni=0; ni<4; ni++){
        const int mcol = wn*32 + ni*8 + lc*2;
        *reinterpret_cast<float2*>(&Out[(size_t)hr*NN + mcol])     = make_float2(acc[mi][ni][0], acc[mi][ni][1]);
        *reinterpret_cast<float2*>(&Out[(size_t)(hr+8)*NN + mcol]) = make_float2(acc[mi][ni][2], acc[mi][ni][3]);
      }
    }
  }
}

// ---------------- gather + bias + relu -------------------------------------
__global__ void k_out(const int* __restrict__ u, const int* __restrict__ v,
                      const float* __restrict__ bias, float* __restrict__ out){
  const int b = blockIdx.x;
  const int h = threadIdx.x;  // 64
  const int ub = u[b], vb = v[b];
  float su = bias[h], sv = bias[h];
  #pragma unroll
  for(int r=0;r<RR;r++){
    su += g_cinv[r*NN + ub] * g_Tu [((size_t)r*NN + ub)*HH + h];
    sv += g_rinv[r*NN + vb] * g_Tvt[((size_t)r*HH + h)*NN + vb];
  }
  out[(size_t)b*HH + h]        = fmaxf(su, 0.f);
  out[(size_t)(BB + b)*HH + h] = fmaxf(sv, 0.f);
}

// ---------------- launch ----------------------------------------------------
extern "C" void kernel_launch(void* const* d_in, const int* in_sizes, int n_in,
                              void* d_out, int out_size){
  (void)in_sizes; (void)n_in; (void)out_size;
  const float* u_feat = (const float*)d_in[0];
  const float* v_feat = (const float*)d_in[1];
  const int*   u      = (const int*)  d_in[2];
  const int*   v      = (const int*)  d_in[3];
  const float* supp   = (const float*)d_in[4];
  const float* u_w    = (const float*)d_in[5];
  const float* v_w    = (const float*)d_in[6];
  const float* u_bias = (const float*)d_in[7];
  float* out = (float*)d_out;

  static int attr_done = 0;
  if(!attr_done){
    cudaFuncSetAttribute(k_gemm, cudaFuncAttributeMaxDynamicSharedMemorySize, DYN_BYTES);
    attr_done = 1;
  }

  k_sums   <<<dim3(32, 16, RR), 128>>>(supp);
  k_reduce <<<160, 256>>>();
  k_weights<<<64, 256>>>(u_w, v_w);
  k_tmp2   <<<dim3(64, RR, 2), 128>>>(u_feat, v_feat);
  k_gemm   <<<dim3(128, RR), 128, DYN_BYTES>>>();
  k_out    <<<BB, HH>>>(u, v, u_bias, out);
}